// round 1
// baseline (speedup 1.0000x reference)
#include <cuda_runtime.h>
#include <math.h>

// Problem constants
#define NN_MAX 100096            // padded node capacity (100000 rounded up)
#define HDIM 128
#define EMAX 3200000

// ---------------- scratch (no allocation allowed -> device globals) ----------
__device__ float g_m[NN_MAX * HDIM];          // x @ W
__device__ float g_gh[NN_MAX * 3 * HDIM];     // x @ gru_w_hh^T + b_hh
__device__ float g_aggsum[NN_MAX * HDIM];     // scatter accumulator
__device__ float g_deg[NN_MAX];               // degree accumulator
__device__ float g_gi[NN_MAX * 3 * HDIM];     // agg @ gru_w_ih^T + b_ih
__device__ float g_hconv[NN_MAX * HDIM];      // GRU output
__device__ float g_gates[NN_MAX * 4 * HDIM];  // lstm gates
__device__ int   g_idx64;                     // 1 if edge_index stored as int64

// ---------------- index-width detection -------------------------------------
// If edge_index is int64 (little-endian), every odd int32 word is the high half
// of a value < 2^31 -> zero. If int32, odd words are random values in [0,1e5):
// probability all 8 samples are zero ~ 1e-40.
__global__ void detect_kernel(const void* edges) {
    const int* p = (const int*)edges;
    int z = 0;
#pragma unroll
    for (int i = 0; i < 8; i++) z += (p[2 * i + 1] == 0) ? 1 : 0;
    g_idx64 = (z == 8) ? 1 : 0;
}

// ---------------- zero accumulators -----------------------------------------
__global__ void zero_kernel(int M) {
    int stride = gridDim.x * blockDim.x;
    int tot = M * HDIM;
    for (int i = blockIdx.x * blockDim.x + threadIdx.x; i < tot; i += stride)
        g_aggsum[i] = 0.0f;
    for (int i = blockIdx.x * blockDim.x + threadIdx.x; i < M; i += stride)
        g_deg[i] = 0.0f;
}

// ---------------- GEMM: C[M,Ncols] = A[M,128] @ B (+bias +bias2) ------------
// TRANSB=false: B is [128, Ncols] row-major (C = A @ B)
// TRANSB=true : B is [Ncols, 128] row-major (C = A @ B^T)
// DIV: A row scaled by 1/max(g_deg[row],1) on load (agg = agg_sum/deg fused)
// Tiles: BM=128 rows x BN=64 cols, 256 threads, 8x4 micro-tile/thread.
// Smem k-major with padded strides (vector-aligned, bounded bank conflicts).
#define BM 128
#define BN 64
#define SA 132   // As[k][m], stride 132 (16B-aligned rows, 4-way store conflict)
#define SB 68    // Bs[k][c], stride 68

template <bool TRANSB, bool DIV>
__global__ __launch_bounds__(256, 2)
void gemm_kernel(const float* __restrict__ A, const float* __restrict__ B,
                 const float* __restrict__ bias, const float* __restrict__ bias2,
                 float* __restrict__ C, int M, int Ncols) {
    extern __shared__ float smem[];
    float* As = smem;                 // [128][SA]
    float* Bs = smem + 128 * SA;      // [128][SB]
    const int tid = threadIdx.x;
    const int row0 = blockIdx.x * BM;
    const int col0 = blockIdx.y * BN;

    // ---- load A tile (128 rows x 128 k), lane-consecutive k for coalescing
#pragma unroll 8
    for (int p = 0; p < 64; p++) {
        int idx = p * 256 + tid;
        int m_ = idx >> 7;
        int k = idx & 127;
        int gr = row0 + m_;
        float v = 0.0f;
        if (gr < M) {
            v = A[(size_t)gr * HDIM + k];
            if (DIV) v *= __frcp_rn(fmaxf(g_deg[gr], 1.0f));
        }
        As[k * SA + m_] = v;
    }

    // ---- load B tile (transpose to k-major in smem)
    if (TRANSB) {
#pragma unroll 8
        for (int p = 0; p < 32; p++) {
            int idx = p * 256 + tid;
            int c = idx >> 7;
            int k = idx & 127;
            Bs[k * SB + c] = B[(size_t)(col0 + c) * HDIM + k];
        }
    } else {
#pragma unroll 8
        for (int p = 0; p < 32; p++) {
            int idx = p * 256 + tid;
            int k = idx >> 6;
            int c = idx & 63;
            Bs[k * SB + c] = B[(size_t)k * Ncols + col0 + c];
        }
    }
    __syncthreads();

    // ---- compute: thread (ty,tx) -> rows r0..r0+7, cols c0..c0+3
    const int r0 = (tid >> 4) * 8;
    const int c0 = (tid & 15) * 4;
    float acc[8][4];
#pragma unroll
    for (int i = 0; i < 8; i++)
#pragma unroll
        for (int j = 0; j < 4; j++) acc[i][j] = 0.0f;

#pragma unroll 4
    for (int k = 0; k < 128; k++) {
        float4 a0 = *(const float4*)(As + k * SA + r0);
        float4 a1 = *(const float4*)(As + k * SA + r0 + 4);
        float4 b = *(const float4*)(Bs + k * SB + c0);
        float av[8] = {a0.x, a0.y, a0.z, a0.w, a1.x, a1.y, a1.z, a1.w};
        float bv[4] = {b.x, b.y, b.z, b.w};
#pragma unroll
        for (int i = 0; i < 8; i++)
#pragma unroll
            for (int j = 0; j < 4; j++) acc[i][j] += av[i] * bv[j];
    }

    // ---- epilogue: bias add + guarded vector store
    float bb[4] = {0.f, 0.f, 0.f, 0.f};
    if (bias) {
#pragma unroll
        for (int j = 0; j < 4; j++) bb[j] += bias[col0 + c0 + j];
    }
    if (bias2) {
#pragma unroll
        for (int j = 0; j < 4; j++) bb[j] += bias2[col0 + c0 + j];
    }
#pragma unroll
    for (int i = 0; i < 8; i++) {
        int gr = row0 + r0 + i;
        if (gr < M) {
            float4 o;
            o.x = acc[i][0] + bb[0];
            o.y = acc[i][1] + bb[1];
            o.z = acc[i][2] + bb[2];
            o.w = acc[i][3] + bb[3];
            *(float4*)(C + (size_t)gr * Ncols + col0 + c0) = o;
        }
    }
}

// ---------------- edge scatter: warp per edge, 16B vector float reductions ---
__global__ void scatter_kernel(const void* __restrict__ edges,
                               const float* __restrict__ m,
                               float* __restrict__ aggsum,
                               float* __restrict__ deg, int E) {
    int gwarp = (blockIdx.x * blockDim.x + threadIdx.x) >> 5;
    int lane = threadIdx.x & 31;
    int nwarp = (gridDim.x * blockDim.x) >> 5;
    const bool is64 = (g_idx64 != 0);
    const long long* p64 = (const long long*)edges;
    const int* p32 = (const int*)edges;
    for (int e = gwarp; e < E; e += nwarp) {
        int src, dst;
        if (is64) {
            src = (int)p64[e];
            dst = (int)p64[E + e];
        } else {
            src = p32[e];
            dst = p32[E + e];
        }
        float4 v = *(const float4*)(m + (size_t)src * HDIM + lane * 4);
        float* addr = aggsum + (size_t)dst * HDIM + lane * 4;
        asm volatile("red.global.add.v4.f32 [%0], {%1, %2, %3, %4};"
                     :: "l"(addr), "f"(v.x), "f"(v.y), "f"(v.z), "f"(v.w)
                     : "memory");
        if (lane == 0) atomicAdd(deg + dst, 1.0f);
    }
}

// ---------------- GRU elementwise: h_conv = (1-z)*tanh(i_n + r*h_n) + z*x ----
__global__ void gru_elem_kernel(const float* __restrict__ x, int M) {
    int i = blockIdx.x * blockDim.x + threadIdx.x;
    if (i >= M * HDIM) return;
    int row = i >> 7;
    int j = i & 127;
    const float* gir = g_gi + (size_t)row * (3 * HDIM);
    const float* ghr = g_gh + (size_t)row * (3 * HDIM);
    float r = 1.0f / (1.0f + expf(-(gir[j] + ghr[j])));
    float z = 1.0f / (1.0f + expf(-(gir[j + 128] + ghr[j + 128])));
    float ng = tanhf(gir[j + 256] + r * ghr[j + 256]);
    g_hconv[i] = (1.0f - z) * ng + z * x[i];
}

// ---------------- LSTM elementwise (c0=h0=0, f-gate dead) + ReLU ------------
__global__ void lstm_elem_kernel(float* __restrict__ out, int M) {
    int i = blockIdx.x * blockDim.x + threadIdx.x;
    if (i >= M * HDIM) return;
    int row = i >> 7;
    int j = i & 127;
    const float* g = g_gates + (size_t)row * (4 * HDIM);
    float ig = g[j];
    float gg = g[j + 256];
    float og = g[j + 384];
    float c = (1.0f / (1.0f + expf(-ig))) * tanhf(gg);
    float h = (1.0f / (1.0f + expf(-og))) * tanhf(c);
    out[i] = fmaxf(h, 0.0f);
}

// ---------------- host orchestration ----------------------------------------
extern "C" void kernel_launch(void* const* d_in, const int* in_sizes, int n_in,
                              void* d_out, int out_size) {
    const float* x = (const float*)d_in[0];
    const void* edges = d_in[1];
    const float* W = (const float*)d_in[2];
    const float* gru_w_ih = (const float*)d_in[3];
    const float* gru_w_hh = (const float*)d_in[4];
    const float* gru_b_ih = (const float*)d_in[5];
    const float* gru_b_hh = (const float*)d_in[6];
    const float* lstm_w_ih = (const float*)d_in[7];
    // d_in[8] lstm_w_hh is dead: h0 = 0
    const float* lstm_b_ih = (const float*)d_in[9];
    const float* lstm_b_hh = (const float*)d_in[10];
    float* out = (float*)d_out;

    const int M = in_sizes[0] / HDIM;   // 100000
    const int E = in_sizes[1] / 2;      // 3200000 (element count is layout-invariant)

    float *pm, *pgh, *pagg, *pdeg, *pgi, *phc, *pgates;
    cudaGetSymbolAddress((void**)&pm, g_m);
    cudaGetSymbolAddress((void**)&pgh, g_gh);
    cudaGetSymbolAddress((void**)&pagg, g_aggsum);
    cudaGetSymbolAddress((void**)&pdeg, g_deg);
    cudaGetSymbolAddress((void**)&pgi, g_gi);
    cudaGetSymbolAddress((void**)&phc, g_hconv);
    cudaGetSymbolAddress((void**)&pgates, g_gates);

    const size_t smem_sz = (size_t)(128 * SA + 128 * SB) * sizeof(float); // 102400
    cudaFuncSetAttribute((const void*)gemm_kernel<false, false>,
                         cudaFuncAttributeMaxDynamicSharedMemorySize, (int)smem_sz);
    cudaFuncSetAttribute((const void*)gemm_kernel<true, false>,
                         cudaFuncAttributeMaxDynamicSharedMemorySize, (int)smem_sz);
    cudaFuncSetAttribute((const void*)gemm_kernel<true, true>,
                         cudaFuncAttributeMaxDynamicSharedMemorySize, (int)smem_sz);

    const int rowTiles = (M + BM - 1) / BM;  // 782

    // 1) index-width flag + zero accumulators
    detect_kernel<<<1, 1>>>(edges);
    zero_kernel<<<2048, 256>>>(M);

    // 2) m = x @ W                         [M,128]
    gemm_kernel<false, false><<<dim3(rowTiles, HDIM / BN), 256, smem_sz>>>(
        x, W, nullptr, nullptr, pm, M, HDIM);

    // 3) gh = x @ gru_w_hh^T + b_hh        [M,384]
    gemm_kernel<true, false><<<dim3(rowTiles, 3 * HDIM / BN), 256, smem_sz>>>(
        x, gru_w_hh, gru_b_hh, nullptr, pgh, M, 3 * HDIM);

    // 4) scatter: aggsum[dst] += m[src]; deg[dst] += 1
    scatter_kernel<<<8192, 256>>>(edges, pm, pagg, pdeg, E);

    // 5) gi = (aggsum/deg) @ gru_w_ih^T + b_ih   [M,384]  (divide fused on load)
    gemm_kernel<true, true><<<dim3(rowTiles, 3 * HDIM / BN), 256, smem_sz>>>(
        pagg, gru_w_ih, gru_b_ih, nullptr, pgi, M, 3 * HDIM);

    // 6) GRU combine -> h_conv             [M,128]
    gru_elem_kernel<<<(M * HDIM + 255) / 256, 256>>>(x, M);

    // 7) gates = h_conv @ lstm_w_ih^T + b_ih + b_hh   [M,512]
    gemm_kernel<true, false><<<dim3(rowTiles, 4 * HDIM / BN), 256, smem_sz>>>(
        phc, lstm_w_ih, lstm_b_ih, lstm_b_hh, pgates, M, 4 * HDIM);

    // 8) LSTM + ReLU -> out                [M,128]
    lstm_elem_kernel<<<(M * HDIM + 255) / 256, 256>>>(out, M);
}

// round 5
// speedup vs baseline: 1.7221x; 1.7221x over previous
#include <cuda_runtime.h>
#include <cuda_bf16.h>
#include <cstdint>
#include <math.h>

// Problem constants
#define NN_MAX 100096
#define HDIM 128

// ---------------- scratch (no allocation allowed -> device globals) ----------
__device__ float g_m[NN_MAX * HDIM];          // x @ W
__device__ float g_gh[NN_MAX * 3 * HDIM];     // x @ gru_w_hh^T + b_hh
__device__ float g_aggsum[NN_MAX * HDIM];     // scatter accumulator
__device__ float g_deg[NN_MAX];               // degree accumulator
__device__ float g_gi[NN_MAX * 3 * HDIM];     // agg @ gru_w_ih^T + b_ih
__device__ float g_hconv[NN_MAX * HDIM];      // GRU output
__device__ float g_gates[NN_MAX * 4 * HDIM];  // lstm gates
__device__ float g_wt[HDIM * HDIM];           // W^T (so all GEMMs use B[c][k])
__device__ int   g_idx64;

// ---------------- index-width detection -------------------------------------
__global__ void detect_kernel(const void* edges) {
    const int* p = (const int*)edges;
    int z = 0;
#pragma unroll
    for (int i = 0; i < 8; i++) z += (p[2 * i + 1] == 0) ? 1 : 0;
    g_idx64 = (z == 8) ? 1 : 0;
}

// ---------------- zero accumulators -----------------------------------------
__global__ void zero_kernel(int M) {
    int stride = gridDim.x * blockDim.x;
    int tot = M * HDIM;
    for (int i = blockIdx.x * blockDim.x + threadIdx.x; i < tot; i += stride)
        g_aggsum[i] = 0.0f;
    for (int i = blockIdx.x * blockDim.x + threadIdx.x; i < M; i += stride)
        g_deg[i] = 0.0f;
}

// ---------------- transpose W (128x128) -------------------------------------
__global__ void transposeW_kernel(const float* __restrict__ W) {
    int i = blockIdx.x * blockDim.x + threadIdx.x;
    if (i < HDIM * HDIM) {
        int r = i >> 7;
        int c = i & 127;
        g_wt[c * HDIM + r] = W[i];
    }
}

// =====================================================================
// bf16x3 tensor-core GEMM: C[M,Ncols] = A[M,128] @ B^T (+bias(+bias2))
//   B given as [Ncols][128] row-major (rows = output cols).
//   A split: hi = bf16(a), lo = bf16(a - hi);
//   C = Ahi*Bhi + Ahi*Blo + Alo*Bhi  (residual ~2^-16).
//   divFlag: scale A row by 1/max(deg,1) on load (fused mean-aggregation).
// Tile: BM=128, BN=64, K=128 single shot. 256 thr = 8 warps (4x2),
// warp tile 32x32 (2 m-atoms x 4 n-atoms of m16n8k16).
// =====================================================================
#define SROW 136                 // bf16 per smem row (272B, conflict-free LDSM)
#define OFF_A_HI 0
#define OFF_A_LO (128 * SROW * 2)
#define OFF_B_HI (2 * 128 * SROW * 2)
#define OFF_B_LO (2 * 128 * SROW * 2 + 64 * SROW * 2)
#define SMEM_BYTES (2 * 128 * SROW * 2 + 2 * 64 * SROW * 2)

__device__ __forceinline__ void ldsm4(uint32_t& r0, uint32_t& r1, uint32_t& r2,
                                      uint32_t& r3, uint32_t addr) {
    asm volatile("ldmatrix.sync.aligned.m8n8.x4.shared.b16 {%0,%1,%2,%3}, [%4];"
                 : "=r"(r0), "=r"(r1), "=r"(r2), "=r"(r3) : "r"(addr));
}

__device__ __forceinline__ void mma_bf16(float* c, const uint32_t* a,
                                         uint32_t b0, uint32_t b1) {
    asm volatile(
        "mma.sync.aligned.m16n8k16.row.col.f32.bf16.bf16.f32 "
        "{%0,%1,%2,%3}, {%4,%5,%6,%7}, {%8,%9}, {%0,%1,%2,%3};"
        : "+f"(c[0]), "+f"(c[1]), "+f"(c[2]), "+f"(c[3])
        : "r"(a[0]), "r"(a[1]), "r"(a[2]), "r"(a[3]), "r"(b0), "r"(b1));
}

__device__ __forceinline__ void split_pack(float x, float y,
                                           uint32_t& hi, uint32_t& lo) {
    __nv_bfloat16 hx = __float2bfloat16_rn(x);
    __nv_bfloat16 hy = __float2bfloat16_rn(y);
    __nv_bfloat16 lx = __float2bfloat16_rn(x - __bfloat162float(hx));
    __nv_bfloat16 ly = __float2bfloat16_rn(y - __bfloat162float(hy));
    hi = ((uint32_t)__bfloat16_as_ushort(hy) << 16) | (uint32_t)__bfloat16_as_ushort(hx);
    lo = ((uint32_t)__bfloat16_as_ushort(ly) << 16) | (uint32_t)__bfloat16_as_ushort(lx);
}

__global__ __launch_bounds__(256, 2)
void mma_gemm_kernel(const float* __restrict__ A, const float* __restrict__ B,
                     const float* __restrict__ bias, const float* __restrict__ bias2,
                     float* __restrict__ C, int M, int Ncols, int divFlag) {
    extern __shared__ char smem[];
    const uint32_t sbase = (uint32_t)__cvta_generic_to_shared(smem);
    const int tid = threadIdx.x;
    const int lane = tid & 31;
    const int wid = tid >> 5;
    const int row0 = blockIdx.x * 128;
    const int col0 = blockIdx.y * 64;

    // ---- load + split A tile: 128 rows x 128 k, 16 float4 per thread -------
    {
        uint32_t* shi = (uint32_t*)(smem + OFF_A_HI);
        uint32_t* slo = (uint32_t*)(smem + OFF_A_LO);
#pragma unroll
        for (int p = 0; p < 16; p++) {
            int idx = p * 256 + tid;          // float4 index
            int row = idx >> 5;
            int k4 = idx & 31;
            int gr = row0 + row;
            float4 v = make_float4(0.f, 0.f, 0.f, 0.f);
            if (gr < M) {
                v = *(const float4*)(A + (size_t)gr * HDIM + k4 * 4);
                if (divFlag) {
                    float r = __frcp_rn(fmaxf(g_deg[gr], 1.0f));
                    v.x *= r; v.y *= r; v.z *= r; v.w *= r;
                }
            }
            uint32_t h0, l0, h1, l1;
            split_pack(v.x, v.y, h0, l0);
            split_pack(v.z, v.w, h1, l1);
            int o = row * (SROW / 2) + k4 * 2;   // u32 index
            shi[o] = h0; shi[o + 1] = h1;
            slo[o] = l0; slo[o + 1] = l1;
        }
    }
    // ---- load + split B tile: 64 rows (output cols) x 128 k ----------------
    {
        uint32_t* shi = (uint32_t*)(smem + OFF_B_HI);
        uint32_t* slo = (uint32_t*)(smem + OFF_B_LO);
#pragma unroll
        for (int p = 0; p < 8; p++) {
            int idx = p * 256 + tid;
            int row = idx >> 5;                 // 0..63
            int k4 = idx & 31;
            float4 v = *(const float4*)(B + (size_t)(col0 + row) * HDIM + k4 * 4);
            uint32_t h0, l0, h1, l1;
            split_pack(v.x, v.y, h0, l0);
            split_pack(v.z, v.w, h1, l1);
            int o = row * (SROW / 2) + k4 * 2;
            shi[o] = h0; shi[o + 1] = h1;
            slo[o] = l0; slo[o + 1] = l1;
        }
    }
    __syncthreads();

    const int wm = wid >> 1;    // 0..3 -> rows wm*32
    const int wn = wid & 1;     // 0..1 -> cols wn*32

    float acc[2][4][4];
#pragma unroll
    for (int i = 0; i < 2; i++)
#pragma unroll
        for (int j = 0; j < 4; j++)
#pragma unroll
            for (int q = 0; q < 4; q++) acc[i][j][q] = 0.0f;

    // ldmatrix per-lane row addressing
    const int a_row_in = ((lane >> 3) & 1) * 8 + (lane & 7);
    const int a_kh = (lane >> 4) * 8;           // bf16 units
    const int b_row_in = ((lane >> 4) & 1) * 8 + (lane & 7);
    const int b_kh = ((lane >> 3) & 1) * 8;

#pragma unroll 2
    for (int kc = 0; kc < 8; kc++) {
        const int k0 = kc * 16;
        uint32_t ah[2][4], al[2][4];
#pragma unroll
        for (int i = 0; i < 2; i++) {
            int row = wm * 32 + i * 16 + a_row_in;
            uint32_t off = (uint32_t)(row * (SROW * 2) + (k0 + a_kh) * 2);
            ldsm4(ah[i][0], ah[i][1], ah[i][2], ah[i][3], sbase + OFF_A_HI + off);
            ldsm4(al[i][0], al[i][1], al[i][2], al[i][3], sbase + OFF_A_LO + off);
        }
        uint32_t bh[2][4], bl[2][4];
#pragma unroll
        for (int p = 0; p < 2; p++) {
            int row = wn * 32 + p * 16 + b_row_in;
            uint32_t off = (uint32_t)(row * (SROW * 2) + (k0 + b_kh) * 2);
            ldsm4(bh[p][0], bh[p][1], bh[p][2], bh[p][3], sbase + OFF_B_HI + off);
            ldsm4(bl[p][0], bl[p][1], bl[p][2], bl[p][3], sbase + OFF_B_LO + off);
        }
#pragma unroll
        for (int i = 0; i < 2; i++) {
#pragma unroll
            for (int j = 0; j < 4; j++) {
                const int p = j >> 1;
                const int s = (j & 1) * 2;
                mma_bf16(acc[i][j], ah[i], bh[p][s], bh[p][s + 1]);
                mma_bf16(acc[i][j], ah[i], bl[p][s], bl[p][s + 1]);
                mma_bf16(acc[i][j], al[i], bh[p][s], bh[p][s + 1]);
            }
        }
    }

    // ---- epilogue: bias + guarded stores ------------------------------------
#pragma unroll
    for (int j = 0; j < 4; j++) {
        int cb = col0 + wn * 32 + j * 8 + (lane & 3) * 2;
        float b0 = 0.f, b1 = 0.f;
        if (bias)  { b0 += __ldg(bias + cb);  b1 += __ldg(bias + cb + 1); }
        if (bias2) { b0 += __ldg(bias2 + cb); b1 += __ldg(bias2 + cb + 1); }
#pragma unroll
        for (int i = 0; i < 2; i++) {
            int ra = row0 + wm * 32 + i * 16 + (lane >> 2);
            if (ra < M) {
                float2 o = make_float2(acc[i][j][0] + b0, acc[i][j][1] + b1);
                *(float2*)(C + (size_t)ra * Ncols + cb) = o;
            }
            int rb = ra + 8;
            if (rb < M) {
                float2 o = make_float2(acc[i][j][2] + b0, acc[i][j][3] + b1);
                *(float2*)(C + (size_t)rb * Ncols + cb) = o;
            }
        }
    }
}

// ---------------- edge scatter: warp per edge, 16B vector float reductions ---
__global__ void scatter_kernel(const void* __restrict__ edges,
                               const float* __restrict__ m,
                               float* __restrict__ aggsum,
                               float* __restrict__ deg, int E) {
    int gwarp = (blockIdx.x * blockDim.x + threadIdx.x) >> 5;
    int lane = threadIdx.x & 31;
    int nwarp = (gridDim.x * blockDim.x) >> 5;
    const bool is64 = (g_idx64 != 0);
    const long long* p64 = (const long long*)edges;
    const int* p32 = (const int*)edges;
    for (int e = gwarp; e < E; e += nwarp) {
        int src, dst;
        if (is64) {
            src = (int)p64[e];
            dst = (int)p64[E + e];
        } else {
            src = p32[e];
            dst = p32[E + e];
        }
        float4 v = *(const float4*)(m + (size_t)src * HDIM + lane * 4);
        float* addr = aggsum + (size_t)dst * HDIM + lane * 4;
        asm volatile("red.global.add.v4.f32 [%0], {%1, %2, %3, %4};"
                     :: "l"(addr), "f"(v.x), "f"(v.y), "f"(v.z), "f"(v.w)
                     : "memory");
        if (lane == 0) atomicAdd(deg + dst, 1.0f);
    }
}

// ---------------- GRU elementwise --------------------------------------------
__global__ void gru_elem_kernel(const float* __restrict__ x, int M) {
    int i = blockIdx.x * blockDim.x + threadIdx.x;
    if (i >= M * HDIM) return;
    int row = i >> 7;
    int j = i & 127;
    const float* gir = g_gi + (size_t)row * (3 * HDIM);
    const float* ghr = g_gh + (size_t)row * (3 * HDIM);
    float r = 1.0f / (1.0f + expf(-(gir[j] + ghr[j])));
    float z = 1.0f / (1.0f + expf(-(gir[j + 128] + ghr[j + 128])));
    float ng = tanhf(gir[j + 256] + r * ghr[j + 256]);
    g_hconv[i] = (1.0f - z) * ng + z * x[i];
}

// ---------------- LSTM elementwise (c0=h0=0) + ReLU --------------------------
__global__ void lstm_elem_kernel(float* __restrict__ out, int M) {
    int i = blockIdx.x * blockDim.x + threadIdx.x;
    if (i >= M * HDIM) return;
    int row = i >> 7;
    int j = i & 127;
    const float* g = g_gates + (size_t)row * (4 * HDIM);
    float ig = g[j];
    float gg = g[j + 256];
    float og = g[j + 384];
    float c = (1.0f / (1.0f + expf(-ig))) * tanhf(gg);
    float h = (1.0f / (1.0f + expf(-og))) * tanhf(c);
    out[i] = fmaxf(h, 0.0f);
}

// ---------------- host orchestration -----------------------------------------
extern "C" void kernel_launch(void* const* d_in, const int* in_sizes, int n_in,
                              void* d_out, int out_size) {
    const float* x = (const float*)d_in[0];
    const void* edges = d_in[1];
    const float* W = (const float*)d_in[2];
    const float* gru_w_ih = (const float*)d_in[3];
    const float* gru_w_hh = (const float*)d_in[4];
    const float* gru_b_ih = (const float*)d_in[5];
    const float* gru_b_hh = (const float*)d_in[6];
    const float* lstm_w_ih = (const float*)d_in[7];
    // d_in[8] lstm_w_hh dead (h0 = 0)
    const float* lstm_b_ih = (const float*)d_in[9];
    const float* lstm_b_hh = (const float*)d_in[10];
    float* out = (float*)d_out;

    const int M = in_sizes[0] / HDIM;
    const int E = in_sizes[1] / 2;

    float *pm, *pgh, *pagg, *pdeg, *pgi, *phc, *pgates, *pwt;
    cudaGetSymbolAddress((void**)&pm, g_m);
    cudaGetSymbolAddress((void**)&pgh, g_gh);
    cudaGetSymbolAddress((void**)&pagg, g_aggsum);
    cudaGetSymbolAddress((void**)&pdeg, g_deg);
    cudaGetSymbolAddress((void**)&pgi, g_gi);
    cudaGetSymbolAddress((void**)&phc, g_hconv);
    cudaGetSymbolAddress((void**)&pgates, g_gates);
    cudaGetSymbolAddress((void**)&pwt, g_wt);

    cudaFuncSetAttribute(mma_gemm_kernel,
                         cudaFuncAttributeMaxDynamicSharedMemorySize, SMEM_BYTES);

    const int rowTiles = (M + 127) / 128;

    // 1) prep
    detect_kernel<<<1, 1>>>(edges);
    zero_kernel<<<2048, 256>>>(M);
    transposeW_kernel<<<(HDIM * HDIM + 255) / 256, 256>>>(W);

    // 2) m = x @ W  (via W^T, B-transposed form)
    mma_gemm_kernel<<<dim3(rowTiles, 2), 256, SMEM_BYTES>>>(
        x, pwt, (const float*)0, (const float*)0, pm, M, HDIM, 0);

    // 3) gh = x @ gru_w_hh^T + b_hh
    mma_gemm_kernel<<<dim3(rowTiles, 6), 256, SMEM_BYTES>>>(
        x, gru_w_hh, gru_b_hh, (const float*)0, pgh, M, 3 * HDIM, 0);

    // 4) scatter mean-agg inputs
    scatter_kernel<<<8192, 256>>>(edges, pm, pagg, pdeg, E);

    // 5) gi = (aggsum/deg) @ gru_w_ih^T + b_ih  (divide fused)
    mma_gemm_kernel<<<dim3(rowTiles, 6), 256, SMEM_BYTES>>>(
        pagg, gru_w_ih, gru_b_ih, (const float*)0, pgi, M, 3 * HDIM, 1);

    // 6) GRU combine
    gru_elem_kernel<<<(M * HDIM + 255) / 256, 256>>>(x, M);

    // 7) gates = h_conv @ lstm_w_ih^T + b_ih + b_hh
    mma_gemm_kernel<<<dim3(rowTiles, 8), 256, SMEM_BYTES>>>(
        phc, lstm_w_ih, lstm_b_ih, lstm_b_hh, pgates, M, 4 * HDIM, 0);

    // 8) LSTM + ReLU
    lstm_elem_kernel<<<(M * HDIM + 255) / 256, 256>>>(out, M);
}

// round 6
// speedup vs baseline: 2.2162x; 1.2870x over previous
#include <cuda_runtime.h>
#include <cuda_bf16.h>
#include <cstdint>
#include <math.h>

// Problem constants
#define NN_MAX 100096
#define HDIM 128
#define EMAX 3400000

// ---------------- scratch (device globals; no allocation allowed) ------------
__device__ float g_m[NN_MAX * HDIM];            // x @ W
__device__ float g_gh[NN_MAX * 3 * HDIM];       // x @ gru_w_hh^T + b_hh
__device__ float g_agg[NN_MAX * HDIM];          // mean-aggregated messages (final)
__device__ float g_gi[NN_MAX * 3 * HDIM];       // agg @ gru_w_ih^T + b_ih
__device__ float g_hconv[NN_MAX * HDIM];        // GRU output
__device__ float g_gates[NN_MAX * 3 * HDIM];    // lstm gates, compact [i,g,o]
__device__ float g_wt[HDIM * HDIM];             // W^T
__device__ int   g_degi[NN_MAX];                // per-dst degree (int)
__device__ int   g_cursor[NN_MAX];              // CSR fill cursors
__device__ int   g_off[NN_MAX + 1];             // CSR offsets
__device__ int   g_csr[EMAX];                   // CSR src indices
__device__ int   g_idx64;

// ---------------- index-width detection --------------------------------------
__global__ void detect_kernel(const void* edges) {
    const int* p = (const int*)edges;
    int z = 0;
#pragma unroll
    for (int i = 0; i < 8; i++) z += (p[2 * i + 1] == 0) ? 1 : 0;
    g_idx64 = (z == 8) ? 1 : 0;
}

// ---------------- zero degree counters ---------------------------------------
__global__ void zero_deg_kernel(int M) {
    int i = blockIdx.x * blockDim.x + threadIdx.x;
    if (i < M) g_degi[i] = 0;
}

// ---------------- transpose W (128x128) --------------------------------------
__global__ void transposeW_kernel(const float* __restrict__ W) {
    int i = blockIdx.x * blockDim.x + threadIdx.x;
    if (i < HDIM * HDIM) {
        int r = i >> 7;
        int c = i & 127;
        g_wt[c * HDIM + r] = W[i];
    }
}

// ---------------- CSR build: histogram ---------------------------------------
__global__ void hist_kernel(const void* __restrict__ edges, int E) {
    const bool is64 = (g_idx64 != 0);
    const long long* p64 = (const long long*)edges;
    const int* p32 = (const int*)edges;
    int stride = gridDim.x * blockDim.x;
    for (int e = blockIdx.x * blockDim.x + threadIdx.x; e < E; e += stride) {
        int dst = is64 ? (int)p64[E + e] : p32[E + e];
        atomicAdd(&g_degi[dst], 1);
    }
}

// ---------------- CSR build: single-block chunked exclusive scan --------------
__global__ void scan_kernel(int M) {
    __shared__ int warpsums[32];
    const int tid = threadIdx.x;
    const int lane = tid & 31;
    const int wid = tid >> 5;
    int running = 0;
    for (int base = 0; base < M; base += 1024) {
        int i = base + tid;
        int v = (i < M) ? g_degi[i] : 0;
        int s = v;
#pragma unroll
        for (int o = 1; o < 32; o <<= 1) {
            int t = __shfl_up_sync(0xffffffffu, s, o);
            if (lane >= o) s += t;
        }
        if (lane == 31) warpsums[wid] = s;
        __syncthreads();
        if (wid == 0) {
            int ws = warpsums[lane];
#pragma unroll
            for (int o = 1; o < 32; o <<= 1) {
                int t = __shfl_up_sync(0xffffffffu, ws, o);
                if (lane >= o) ws += t;
            }
            warpsums[lane] = ws;
        }
        __syncthreads();
        int warpBase = (wid == 0) ? 0 : warpsums[wid - 1];
        int excl = running + warpBase + s - v;
        if (i < M) {
            g_off[i] = excl;
            g_cursor[i] = excl;
        }
        int chunkTotal = warpsums[31];
        __syncthreads();
        running += chunkTotal;
    }
    if (tid == 0) g_off[M] = running;
}

// ---------------- CSR build: fill src lists ----------------------------------
__global__ void fill_kernel(const void* __restrict__ edges, int E) {
    const bool is64 = (g_idx64 != 0);
    const long long* p64 = (const long long*)edges;
    const int* p32 = (const int*)edges;
    int stride = gridDim.x * blockDim.x;
    for (int e = blockIdx.x * blockDim.x + threadIdx.x; e < E; e += stride) {
        int src, dst;
        if (is64) {
            src = (int)p64[e];
            dst = (int)p64[E + e];
        } else {
            src = p32[e];
            dst = p32[E + e];
        }
        int pos = atomicAdd(&g_cursor[dst], 1);
        g_csr[pos] = src;
    }
}

// ---------------- gather: one warp per dst, mean fused ------------------------
__global__ void gather_kernel(const float* __restrict__ m, int M) {
    int w = (blockIdx.x * blockDim.x + threadIdx.x) >> 5;
    if (w >= M) return;
    int lane = threadIdx.x & 31;
    int start = g_off[w];
    int end = g_off[w + 1];
    float ax = 0.f, ay = 0.f, az = 0.f, aw = 0.f;
    int e = start;
    for (; e + 1 < end; e += 2) {
        int s0 = g_csr[e];
        int s1 = g_csr[e + 1];
        float4 a = *(const float4*)(m + (size_t)s0 * HDIM + lane * 4);
        float4 b = *(const float4*)(m + (size_t)s1 * HDIM + lane * 4);
        ax += a.x + b.x; ay += a.y + b.y; az += a.z + b.z; aw += a.w + b.w;
    }
    if (e < end) {
        int s0 = g_csr[e];
        float4 a = *(const float4*)(m + (size_t)s0 * HDIM + lane * 4);
        ax += a.x; ay += a.y; az += a.z; aw += a.w;
    }
    float inv = 1.0f / fmaxf((float)(end - start), 1.0f);
    float4 o = make_float4(ax * inv, ay * inv, az * inv, aw * inv);
    *(float4*)(g_agg + (size_t)w * HDIM + lane * 4) = o;
}

// =====================================================================
// bf16x3 tensor-core GEMM with in-block column-tile loop (A loaded once).
// C[M, nTiles*64] = A[M,128] @ B^T (+bias(+bias2)); B rows = output cols.
// gateSkip: tile t -> B row block {0,64,256,320,384,448} (skip dead f-gate),
//           output stays compact at col t*64.
// =====================================================================
#define SROW 136
#define OFF_A_HI 0
#define OFF_A_LO (128 * SROW * 2)
#define OFF_B_HI (2 * 128 * SROW * 2)
#define OFF_B_LO (2 * 128 * SROW * 2 + 64 * SROW * 2)
#define SMEM_BYTES (2 * 128 * SROW * 2 + 2 * 64 * SROW * 2)

__device__ __forceinline__ void ldsm4(uint32_t& r0, uint32_t& r1, uint32_t& r2,
                                      uint32_t& r3, uint32_t addr) {
    asm volatile("ldmatrix.sync.aligned.m8n8.x4.shared.b16 {%0,%1,%2,%3}, [%4];"
                 : "=r"(r0), "=r"(r1), "=r"(r2), "=r"(r3) : "r"(addr));
}

__device__ __forceinline__ void mma_bf16(float* c, const uint32_t* a,
                                         uint32_t b0, uint32_t b1) {
    asm volatile(
        "mma.sync.aligned.m16n8k16.row.col.f32.bf16.bf16.f32 "
        "{%0,%1,%2,%3}, {%4,%5,%6,%7}, {%8,%9}, {%0,%1,%2,%3};"
        : "+f"(c[0]), "+f"(c[1]), "+f"(c[2]), "+f"(c[3])
        : "r"(a[0]), "r"(a[1]), "r"(a[2]), "r"(a[3]), "r"(b0), "r"(b1));
}

__device__ __forceinline__ void split_pack(float x, float y,
                                           uint32_t& hi, uint32_t& lo) {
    __nv_bfloat16 hx = __float2bfloat16_rn(x);
    __nv_bfloat16 hy = __float2bfloat16_rn(y);
    __nv_bfloat16 lx = __float2bfloat16_rn(x - __bfloat162float(hx));
    __nv_bfloat16 ly = __float2bfloat16_rn(y - __bfloat162float(hy));
    hi = ((uint32_t)__bfloat16_as_ushort(hy) << 16) | (uint32_t)__bfloat16_as_ushort(hx);
    lo = ((uint32_t)__bfloat16_as_ushort(ly) << 16) | (uint32_t)__bfloat16_as_ushort(lx);
}

__global__ __launch_bounds__(256, 2)
void mma_gemm_kernel(const float* __restrict__ A, const float* __restrict__ B,
                     const float* __restrict__ bias, const float* __restrict__ bias2,
                     float* __restrict__ C, int M, int NcolsOut, int nTiles,
                     int gateSkip) {
    extern __shared__ char smem[];
    const uint32_t sbase = (uint32_t)__cvta_generic_to_shared(smem);
    const int tid = threadIdx.x;
    const int lane = tid & 31;
    const int wid = tid >> 5;
    const int row0 = blockIdx.x * 128;

    // ---- load + split A tile ONCE: 128 rows x 128 k -------------------------
    {
        uint32_t* shi = (uint32_t*)(smem + OFF_A_HI);
        uint32_t* slo = (uint32_t*)(smem + OFF_A_LO);
#pragma unroll
        for (int p = 0; p < 16; p++) {
            int idx = p * 256 + tid;
            int row = idx >> 5;
            int k4 = idx & 31;
            int gr = row0 + row;
            float4 v = make_float4(0.f, 0.f, 0.f, 0.f);
            if (gr < M) v = *(const float4*)(A + (size_t)gr * HDIM + k4 * 4);
            uint32_t h0, l0, h1, l1;
            split_pack(v.x, v.y, h0, l0);
            split_pack(v.z, v.w, h1, l1);
            int o = row * (SROW / 2) + k4 * 2;
            shi[o] = h0; shi[o + 1] = h1;
            slo[o] = l0; slo[o + 1] = l1;
        }
    }

    const int wm = wid >> 1;
    const int wn = wid & 1;
    const int a_row_in = ((lane >> 3) & 1) * 8 + (lane & 7);
    const int a_kh = (lane >> 4) * 8;
    const int b_row_in = ((lane >> 4) & 1) * 8 + (lane & 7);
    const int b_kh = ((lane >> 3) & 1) * 8;

    for (int t = 0; t < nTiles; t++) {
        const int brow0 = gateSkip ? ((t < 2) ? t * 64 : (t + 2) * 64) : t * 64;
        const int ccol0 = t * 64;

        if (t > 0) __syncthreads();   // previous compute done before B overwrite

        // ---- load + split B tile: 64 rows x 128 k ---------------------------
        {
            uint32_t* shi = (uint32_t*)(smem + OFF_B_HI);
            uint32_t* slo = (uint32_t*)(smem + OFF_B_LO);
#pragma unroll
            for (int p = 0; p < 8; p++) {
                int idx = p * 256 + tid;
                int row = idx >> 5;
                int k4 = idx & 31;
                float4 v = *(const float4*)(B + (size_t)(brow0 + row) * HDIM + k4 * 4);
                uint32_t h0, l0, h1, l1;
                split_pack(v.x, v.y, h0, l0);
                split_pack(v.z, v.w, h1, l1);
                int o = row * (SROW / 2) + k4 * 2;
                shi[o] = h0; shi[o + 1] = h1;
                slo[o] = l0; slo[o + 1] = l1;
            }
        }
        __syncthreads();

        float acc[2][4][4];
#pragma unroll
        for (int i = 0; i < 2; i++)
#pragma unroll
            for (int j = 0; j < 4; j++)
#pragma unroll
                for (int q = 0; q < 4; q++) acc[i][j][q] = 0.0f;

#pragma unroll 2
        for (int kc = 0; kc < 8; kc++) {
            const int k0 = kc * 16;
            uint32_t ah[2][4], al[2][4];
#pragma unroll
            for (int i = 0; i < 2; i++) {
                int row = wm * 32 + i * 16 + a_row_in;
                uint32_t off = (uint32_t)(row * (SROW * 2) + (k0 + a_kh) * 2);
                ldsm4(ah[i][0], ah[i][1], ah[i][2], ah[i][3], sbase + OFF_A_HI + off);
                ldsm4(al[i][0], al[i][1], al[i][2], al[i][3], sbase + OFF_A_LO + off);
            }
            uint32_t bh[2][4], bl[2][4];
#pragma unroll
            for (int p = 0; p < 2; p++) {
                int row = wn * 32 + p * 16 + b_row_in;
                uint32_t off = (uint32_t)(row * (SROW * 2) + (k0 + b_kh) * 2);
                ldsm4(bh[p][0], bh[p][1], bh[p][2], bh[p][3], sbase + OFF_B_HI + off);
                ldsm4(bl[p][0], bl[p][1], bl[p][2], bl[p][3], sbase + OFF_B_LO + off);
            }
#pragma unroll
            for (int i = 0; i < 2; i++) {
#pragma unroll
                for (int j = 0; j < 4; j++) {
                    const int p = j >> 1;
                    const int s = (j & 1) * 2;
                    mma_bf16(acc[i][j], ah[i], bh[p][s], bh[p][s + 1]);
                    mma_bf16(acc[i][j], ah[i], bl[p][s], bl[p][s + 1]);
                    mma_bf16(acc[i][j], al[i], bh[p][s], bh[p][s + 1]);
                }
            }
        }

        // ---- epilogue -------------------------------------------------------
#pragma unroll
        for (int j = 0; j < 4; j++) {
            int cloc = wn * 32 + j * 8 + (lane & 3) * 2;
            int cb = ccol0 + cloc;          // output column (compact)
            int bidx = brow0 + cloc;        // bias index (gate-space)
            float b0 = 0.f, b1 = 0.f;
            if (bias)  { b0 += __ldg(bias + bidx);  b1 += __ldg(bias + bidx + 1); }
            if (bias2) { b0 += __ldg(bias2 + bidx); b1 += __ldg(bias2 + bidx + 1); }
#pragma unroll
            for (int i = 0; i < 2; i++) {
                int ra = row0 + wm * 32 + i * 16 + (lane >> 2);
                if (ra < M) {
                    float2 o = make_float2(acc[i][j][0] + b0, acc[i][j][1] + b1);
                    *(float2*)(C + (size_t)ra * NcolsOut + cb) = o;
                }
                int rb = ra + 8;
                if (rb < M) {
                    float2 o = make_float2(acc[i][j][2] + b0, acc[i][j][3] + b1);
                    *(float2*)(C + (size_t)rb * NcolsOut + cb) = o;
                }
            }
        }
    }
}

// ---------------- GRU elementwise --------------------------------------------
__global__ void gru_elem_kernel(const float* __restrict__ x, int M) {
    int i = blockIdx.x * blockDim.x + threadIdx.x;
    if (i >= M * HDIM) return;
    int row = i >> 7;
    int j = i & 127;
    const float* gir = g_gi + (size_t)row * (3 * HDIM);
    const float* ghr = g_gh + (size_t)row * (3 * HDIM);
    float r = 1.0f / (1.0f + expf(-(gir[j] + ghr[j])));
    float z = 1.0f / (1.0f + expf(-(gir[j + 128] + ghr[j + 128])));
    float ng = tanhf(gir[j + 256] + r * ghr[j + 256]);
    g_hconv[i] = (1.0f - z) * ng + z * x[i];
}

// ---------------- LSTM elementwise (compact [i,g,o] gates) + ReLU ------------
__global__ void lstm_elem_kernel(float* __restrict__ out, int M) {
    int i = blockIdx.x * blockDim.x + threadIdx.x;
    if (i >= M * HDIM) return;
    int row = i >> 7;
    int j = i & 127;
    const float* g = g_gates + (size_t)row * (3 * HDIM);
    float ig = g[j];
    float gg = g[j + 128];
    float og = g[j + 256];
    float c = (1.0f / (1.0f + expf(-ig))) * tanhf(gg);
    float h = (1.0f / (1.0f + expf(-og))) * tanhf(c);
    out[i] = fmaxf(h, 0.0f);
}

// ---------------- host orchestration -----------------------------------------
extern "C" void kernel_launch(void* const* d_in, const int* in_sizes, int n_in,
                              void* d_out, int out_size) {
    const float* x = (const float*)d_in[0];
    const void* edges = d_in[1];
    const float* W = (const float*)d_in[2];
    const float* gru_w_ih = (const float*)d_in[3];
    const float* gru_w_hh = (const float*)d_in[4];
    const float* gru_b_ih = (const float*)d_in[5];
    const float* gru_b_hh = (const float*)d_in[6];
    const float* lstm_w_ih = (const float*)d_in[7];
    // d_in[8] lstm_w_hh dead (h0 = 0)
    const float* lstm_b_ih = (const float*)d_in[9];
    const float* lstm_b_hh = (const float*)d_in[10];
    float* out = (float*)d_out;

    const int M = in_sizes[0] / HDIM;
    const int E = in_sizes[1] / 2;

    float *pm, *pgh, *pagg, *pgi, *phc, *pgates, *pwt;
    cudaGetSymbolAddress((void**)&pm, g_m);
    cudaGetSymbolAddress((void**)&pgh, g_gh);
    cudaGetSymbolAddress((void**)&pagg, g_agg);
    cudaGetSymbolAddress((void**)&pgi, g_gi);
    cudaGetSymbolAddress((void**)&phc, g_hconv);
    cudaGetSymbolAddress((void**)&pgates, g_gates);
    cudaGetSymbolAddress((void**)&pwt, g_wt);

    cudaFuncSetAttribute(mma_gemm_kernel,
                         cudaFuncAttributeMaxDynamicSharedMemorySize, SMEM_BYTES);

    const int rowTiles = (M + 127) / 128;

    // 1) prep
    detect_kernel<<<1, 1>>>(edges);
    zero_deg_kernel<<<(M + 255) / 256, 256>>>(M);
    transposeW_kernel<<<(HDIM * HDIM + 255) / 256, 256>>>(W);

    // 2) m = x @ W
    mma_gemm_kernel<<<rowTiles, 256, SMEM_BYTES>>>(
        x, pwt, (const float*)0, (const float*)0, pm, M, HDIM, 2, 0);

    // 3) gh = x @ gru_w_hh^T + b_hh
    mma_gemm_kernel<<<rowTiles, 256, SMEM_BYTES>>>(
        x, gru_w_hh, gru_b_hh, (const float*)0, pgh, M, 3 * HDIM, 6, 0);

    // 4) CSR build + gather (mean fused)
    hist_kernel<<<4096, 256>>>(edges, E);
    scan_kernel<<<1, 1024>>>(M);
    fill_kernel<<<4096, 256>>>(edges, E);
    gather_kernel<<<(M * 32 + 255) / 256, 256>>>(pm, M);

    // 5) gi = agg @ gru_w_ih^T + b_ih
    mma_gemm_kernel<<<rowTiles, 256, SMEM_BYTES>>>(
        pagg, gru_w_ih, gru_b_ih, (const float*)0, pgi, M, 3 * HDIM, 6, 0);

    // 6) GRU combine
    gru_elem_kernel<<<(M * HDIM + 255) / 256, 256>>>(x, M);

    // 7) gates = h_conv @ lstm_w_ih^T + b (f-gate skipped, compact [i,g,o])
    mma_gemm_kernel<<<rowTiles, 256, SMEM_BYTES>>>(
        phc, lstm_w_ih, lstm_b_ih, lstm_b_hh, pgates, M, 3 * HDIM, 6, 1);

    // 8) LSTM + ReLU
    lstm_elem_kernel<<<(M * HDIM + 255) / 256, 256>>>(out, M);
}

// round 9
// speedup vs baseline: 2.2242x; 1.0036x over previous
#include <cuda_runtime.h>
#include <cuda_bf16.h>
#include <cstdint>
#include <math.h>

// Problem constants
#define NN_MAX 100096
#define HDIM 128
#define EMAX 3400000

// ---------------- scratch (device globals; no allocation allowed) ------------
__device__ float g_m[NN_MAX * HDIM];            // x @ W
__device__ float g_gh[NN_MAX * 3 * HDIM];       // x @ gru_w_hh^T + b_hh
__device__ float g_agg[NN_MAX * HDIM];          // mean-aggregated messages
__device__ float g_gi[NN_MAX * 3 * HDIM];       // agg @ gru_w_ih^T + b_ih
__device__ float g_hconv[NN_MAX * HDIM];        // GRU output
__device__ float g_gates[NN_MAX * 3 * HDIM];    // lstm gates, compact [i,g,o]
__device__ float g_wt[HDIM * HDIM];             // W^T
__device__ int   g_degi[NN_MAX];
__device__ int   g_cursor[NN_MAX];
__device__ int   g_off[NN_MAX + 1];
__device__ int   g_csr[EMAX];
__device__ int   g_idx64;

// ---------------- index-width detection --------------------------------------
__global__ void detect_kernel(const void* edges) {
    const int* p = (const int*)edges;
    int z = 0;
#pragma unroll
    for (int i = 0; i < 8; i++) z += (p[2 * i + 1] == 0) ? 1 : 0;
    g_idx64 = (z == 8) ? 1 : 0;
}

__global__ void zero_deg_kernel(int M) {
    int i = blockIdx.x * blockDim.x + threadIdx.x;
    if (i < M) g_degi[i] = 0;
}

__global__ void transposeW_kernel(const float* __restrict__ W) {
    int i = blockIdx.x * blockDim.x + threadIdx.x;
    if (i < HDIM * HDIM) {
        int r = i >> 7;
        int c = i & 127;
        g_wt[c * HDIM + r] = W[i];
    }
}

// ---------------- CSR build -----------------------------------------------
__global__ void hist_kernel(const void* __restrict__ edges, int E) {
    const bool is64 = (g_idx64 != 0);
    const long long* p64 = (const long long*)edges;
    const int* p32 = (const int*)edges;
    int stride = gridDim.x * blockDim.x;
    for (int e = blockIdx.x * blockDim.x + threadIdx.x; e < E; e += stride) {
        int dst = is64 ? (int)p64[E + e] : p32[E + e];
        atomicAdd(&g_degi[dst], 1);
    }
}

__global__ void scan_kernel(int M) {
    __shared__ int warpsums[32];
    const int tid = threadIdx.x;
    const int lane = tid & 31;
    const int wid = tid >> 5;
    int running = 0;
    for (int base = 0; base < M; base += 1024) {
        int i = base + tid;
        int v = (i < M) ? g_degi[i] : 0;
        int s = v;
#pragma unroll
        for (int o = 1; o < 32; o <<= 1) {
            int t = __shfl_up_sync(0xffffffffu, s, o);
            if (lane >= o) s += t;
        }
        if (lane == 31) warpsums[wid] = s;
        __syncthreads();
        if (wid == 0) {
            int ws = warpsums[lane];
#pragma unroll
            for (int o = 1; o < 32; o <<= 1) {
                int t = __shfl_up_sync(0xffffffffu, ws, o);
                if (lane >= o) ws += t;
            }
            warpsums[lane] = ws;
        }
        __syncthreads();
        int warpBase = (wid == 0) ? 0 : warpsums[wid - 1];
        int excl = running + warpBase + s - v;
        if (i < M) {
            g_off[i] = excl;
            g_cursor[i] = excl;
        }
        int chunkTotal = warpsums[31];
        __syncthreads();
        running += chunkTotal;
    }
    if (tid == 0) g_off[M] = running;
}

__global__ void fill_kernel(const void* __restrict__ edges, int E) {
    const bool is64 = (g_idx64 != 0);
    const long long* p64 = (const long long*)edges;
    const int* p32 = (const int*)edges;
    int stride = gridDim.x * blockDim.x;
    for (int e = blockIdx.x * blockDim.x + threadIdx.x; e < E; e += stride) {
        int src, dst;
        if (is64) {
            src = (int)p64[e];
            dst = (int)p64[E + e];
        } else {
            src = p32[e];
            dst = p32[E + e];
        }
        int pos = atomicAdd(&g_cursor[dst], 1);
        g_csr[pos] = src;
    }
}

// ---------------- gather: one warp per dst, mean fused ------------------------
__global__ void gather_kernel(const float* __restrict__ m, int M) {
    int w = (blockIdx.x * blockDim.x + threadIdx.x) >> 5;
    if (w >= M) return;
    int lane = threadIdx.x & 31;
    int start = g_off[w];
    int end = g_off[w + 1];
    float ax = 0.f, ay = 0.f, az = 0.f, aw = 0.f;
    int e = start;
    for (; e + 1 < end; e += 2) {
        int s0 = g_csr[e];
        int s1 = g_csr[e + 1];
        float4 a = *(const float4*)(m + (size_t)s0 * HDIM + lane * 4);
        float4 b = *(const float4*)(m + (size_t)s1 * HDIM + lane * 4);
        ax += a.x + b.x; ay += a.y + b.y; az += a.z + b.z; aw += a.w + b.w;
    }
    if (e < end) {
        int s0 = g_csr[e];
        float4 a = *(const float4*)(m + (size_t)s0 * HDIM + lane * 4);
        ax += a.x; ay += a.y; az += a.z; aw += a.w;
    }
    float inv = 1.0f / fmaxf((float)(end - start), 1.0f);
    float4 o = make_float4(ax * inv, ay * inv, az * inv, aw * inv);
    *(float4*)(g_agg + (size_t)w * HDIM + lane * 4) = o;
}

// =====================================================================
// bf16x3 tensor-core GEMM, in-block col-tile loop, B-tile register
// prefetch, optional fused GRU/LSTM epilogue.
//   epi = 0: plain; epi = 1: GRU readback -> hconv; epi = 2: LSTM -> out
// gateSkip: tile t reads B rows {0,64,256,320,384,448}[t] (skip f-gate).
// B tile per-thread mapping: row = (tid>>5) + p*8, k4 = tid&31  (64 rows).
// =====================================================================
#define SROW 136
#define OFF_A_HI 0
#define OFF_A_LO (128 * SROW * 2)
#define OFF_B_HI (2 * 128 * SROW * 2)
#define OFF_B_LO (2 * 128 * SROW * 2 + 64 * SROW * 2)
#define SMEM_BYTES (2 * 128 * SROW * 2 + 2 * 64 * SROW * 2)

__device__ __forceinline__ void ldsm4(uint32_t& r0, uint32_t& r1, uint32_t& r2,
                                      uint32_t& r3, uint32_t addr) {
    asm volatile("ldmatrix.sync.aligned.m8n8.x4.shared.b16 {%0,%1,%2,%3}, [%4];"
                 : "=r"(r0), "=r"(r1), "=r"(r2), "=r"(r3) : "r"(addr));
}

__device__ __forceinline__ void mma_bf16(float* c, const uint32_t* a,
                                         uint32_t b0, uint32_t b1) {
    asm volatile(
        "mma.sync.aligned.m16n8k16.row.col.f32.bf16.bf16.f32 "
        "{%0,%1,%2,%3}, {%4,%5,%6,%7}, {%8,%9}, {%0,%1,%2,%3};"
        : "+f"(c[0]), "+f"(c[1]), "+f"(c[2]), "+f"(c[3])
        : "r"(a[0]), "r"(a[1]), "r"(a[2]), "r"(a[3]), "r"(b0), "r"(b1));
}

__device__ __forceinline__ void split_pack(float x, float y,
                                           uint32_t& hi, uint32_t& lo) {
    __nv_bfloat16 hx = __float2bfloat16_rn(x);
    __nv_bfloat16 hy = __float2bfloat16_rn(y);
    __nv_bfloat16 lx = __float2bfloat16_rn(x - __bfloat162float(hx));
    __nv_bfloat16 ly = __float2bfloat16_rn(y - __bfloat162float(hy));
    hi = ((uint32_t)__bfloat16_as_ushort(hy) << 16) | (uint32_t)__bfloat16_as_ushort(hx);
    lo = ((uint32_t)__bfloat16_as_ushort(ly) << 16) | (uint32_t)__bfloat16_as_ushort(lx);
}

__device__ __forceinline__ float sigf(float v) {
    return 1.0f / (1.0f + expf(-v));
}

__global__ __launch_bounds__(256, 2)
void mma_gemm_kernel(const float* __restrict__ A, const float* __restrict__ B,
                     const float* __restrict__ bias, const float* __restrict__ bias2,
                     float* __restrict__ C, int M, int NcolsOut, int nTiles,
                     int gateSkip, int epi,
                     const float* __restrict__ aux1,
                     const float* __restrict__ aux2,
                     float* __restrict__ aux3) {
    extern __shared__ char smem[];
    const uint32_t sbase = (uint32_t)__cvta_generic_to_shared(smem);
    const int tid = threadIdx.x;
    const int lane = tid & 31;
    const int wid = tid >> 5;
    const int row0 = blockIdx.x * 128;

    // ---- load + split A tile ONCE -------------------------------------------
    {
        uint32_t* shi = (uint32_t*)(smem + OFF_A_HI);
        uint32_t* slo = (uint32_t*)(smem + OFF_A_LO);
#pragma unroll
        for (int p = 0; p < 16; p++) {
            int idx = p * 256 + tid;
            int row = idx >> 5;
            int k4 = idx & 31;
            int gr = row0 + row;
            float4 v = make_float4(0.f, 0.f, 0.f, 0.f);
            if (gr < M) v = *(const float4*)(A + (size_t)gr * HDIM + k4 * 4);
            uint32_t h0, l0, h1, l1;
            split_pack(v.x, v.y, h0, l0);
            split_pack(v.z, v.w, h1, l1);
            int o = row * (SROW / 2) + k4 * 2;
            shi[o] = h0; shi[o + 1] = h1;
            slo[o] = l0; slo[o + 1] = l1;
        }
    }

    const int wm = wid >> 1;
    const int wn = wid & 1;
    const int a_row_in = ((lane >> 3) & 1) * 8 + (lane & 7);
    const int a_kh = (lane >> 4) * 8;
    const int b_row_in = ((lane >> 4) & 1) * 8 + (lane & 7);
    const int b_kh = ((lane >> 3) & 1) * 8;

    // per-thread B coords: row = bp_row + p*8 (0..63), k4 = bp_k4
    const int bp_row = tid >> 5;        // 0..7
    const int bp_k4 = tid & 31;

    // prefetch registers for B tile 0 (row base 0 for all launches)
    float4 bpre[8];
#pragma unroll
    for (int p = 0; p < 8; p++)
        bpre[p] = *(const float4*)(B + (size_t)(bp_row + p * 8) * HDIM + bp_k4 * 4);

    for (int t = 0; t < nTiles; t++) {
        const int brow0 = gateSkip ? ((t < 2) ? t * 64 : (t + 2) * 64) : t * 64;
        const int ccol0 = t * 64;

        if (t > 0) __syncthreads();   // previous compute done before B overwrite

        // ---- store + split prefetched B tile to smem ------------------------
        {
            uint32_t* shi = (uint32_t*)(smem + OFF_B_HI);
            uint32_t* slo = (uint32_t*)(smem + OFF_B_LO);
#pragma unroll
            for (int p = 0; p < 8; p++) {
                float4 v = bpre[p];
                uint32_t h0, l0, h1, l1;
                split_pack(v.x, v.y, h0, l0);
                split_pack(v.z, v.w, h1, l1);
                int o = (bp_row + p * 8) * (SROW / 2) + bp_k4 * 2;
                shi[o] = h0; shi[o + 1] = h1;
                slo[o] = l0; slo[o + 1] = l1;
            }
        }
        __syncthreads();

        // ---- issue prefetch for NEXT tile before compute --------------------
        if (t + 1 < nTiles) {
            const int nrow0 = gateSkip ? ((t + 1 < 2) ? (t + 1) * 64 : (t + 3) * 64)
                                       : (t + 1) * 64;
#pragma unroll
            for (int p = 0; p < 8; p++)
                bpre[p] = *(const float4*)(B + (size_t)(nrow0 + bp_row + p * 8) * HDIM + bp_k4 * 4);
        }

        float acc[2][4][4];
#pragma unroll
        for (int i = 0; i < 2; i++)
#pragma unroll
            for (int j = 0; j < 4; j++)
#pragma unroll
                for (int q = 0; q < 4; q++) acc[i][j][q] = 0.0f;

#pragma unroll 2
        for (int kc = 0; kc < 8; kc++) {
            const int k0 = kc * 16;
            uint32_t ah[2][4], al[2][4];
#pragma unroll
            for (int i = 0; i < 2; i++) {
                int row = wm * 32 + i * 16 + a_row_in;
                uint32_t off = (uint32_t)(row * (SROW * 2) + (k0 + a_kh) * 2);
                ldsm4(ah[i][0], ah[i][1], ah[i][2], ah[i][3], sbase + OFF_A_HI + off);
                ldsm4(al[i][0], al[i][1], al[i][2], al[i][3], sbase + OFF_A_LO + off);
            }
            uint32_t bh[2][4], bl[2][4];
#pragma unroll
            for (int p = 0; p < 2; p++) {
                int row = wn * 32 + p * 16 + b_row_in;
                uint32_t off = (uint32_t)(row * (SROW * 2) + (k0 + b_kh) * 2);
                ldsm4(bh[p][0], bh[p][1], bh[p][2], bh[p][3], sbase + OFF_B_HI + off);
                ldsm4(bl[p][0], bl[p][1], bl[p][2], bl[p][3], sbase + OFF_B_LO + off);
            }
#pragma unroll
            for (int i = 0; i < 2; i++) {
#pragma unroll
                for (int j = 0; j < 4; j++) {
                    const int p = j >> 1;
                    const int s = (j & 1) * 2;
                    mma_bf16(acc[i][j], ah[i], bh[p][s], bh[p][s + 1]);
                    mma_bf16(acc[i][j], ah[i], bl[p][s], bl[p][s + 1]);
                    mma_bf16(acc[i][j], al[i], bh[p][s], bh[p][s + 1]);
                }
            }
        }

        // ---- store tile -----------------------------------------------------
#pragma unroll
        for (int j = 0; j < 4; j++) {
            int cloc = wn * 32 + j * 8 + (lane & 3) * 2;
            int cb = ccol0 + cloc;
            int bidx = brow0 + cloc;
            float b0 = 0.f, b1 = 0.f;
            if (bias)  { b0 += __ldg(bias + bidx);  b1 += __ldg(bias + bidx + 1); }
            if (bias2) { b0 += __ldg(bias2 + bidx); b1 += __ldg(bias2 + bidx + 1); }
#pragma unroll
            for (int i = 0; i < 2; i++) {
                int ra = row0 + wm * 32 + i * 16 + (lane >> 2);
                if (ra < M) {
                    float2 o = make_float2(acc[i][j][0] + b0, acc[i][j][1] + b1);
                    *(float2*)(C + (size_t)ra * NcolsOut + cb) = o;
                }
                int rb = ra + 8;
                if (rb < M) {
                    float2 o = make_float2(acc[i][j][2] + b0, acc[i][j][3] + b1);
                    *(float2*)(C + (size_t)rb * NcolsOut + cb) = o;
                }
            }
        }
    }

    // ---- fused elementwise epilogue (block's rows, C now L2-hot) -------------
    if (epi == 0) return;
    __syncthreads();   // all tiles of this block's rows stored & visible

    if (epi == 1) {
        // GRU: r=sig(gi_r+gh_r); z=sig(gi_z+gh_z); n=tanh(gi_n+r*gh_n);
        //      hconv = (1-z)*n + z*x
#pragma unroll
        for (int p = 0; p < 16; p++) {
            int idx = p * 256 + tid;          // 128 rows x 32 float4
            int row = idx >> 5;
            int c4 = idx & 31;
            int gr = row0 + row;
            if (gr >= M) continue;
            const float* cr = C + (size_t)gr * 384 + c4 * 4;
            const float* hr = aux1 + (size_t)gr * 384 + c4 * 4;
            float4 gi_r = __ldcg((const float4*)(cr));
            float4 gi_z = __ldcg((const float4*)(cr + 128));
            float4 gi_n = __ldcg((const float4*)(cr + 256));
            float4 gh_r = __ldg((const float4*)(hr));
            float4 gh_z = __ldg((const float4*)(hr + 128));
            float4 gh_n = __ldg((const float4*)(hr + 256));
            float4 xv = __ldg((const float4*)(aux2 + (size_t)gr * HDIM + c4 * 4));
            float4 o;
            {
                float r = sigf(gi_r.x + gh_r.x);
                float z = sigf(gi_z.x + gh_z.x);
                float n = tanhf(gi_n.x + r * gh_n.x);
                o.x = (1.0f - z) * n + z * xv.x;
            }
            {
                float r = sigf(gi_r.y + gh_r.y);
                float z = sigf(gi_z.y + gh_z.y);
                float n = tanhf(gi_n.y + r * gh_n.y);
                o.y = (1.0f - z) * n + z * xv.y;
            }
            {
                float r = sigf(gi_r.z + gh_r.z);
                float z = sigf(gi_z.z + gh_z.z);
                float n = tanhf(gi_n.z + r * gh_n.z);
                o.z = (1.0f - z) * n + z * xv.z;
            }
            {
                float r = sigf(gi_r.w + gh_r.w);
                float z = sigf(gi_z.w + gh_z.w);
                float n = tanhf(gi_n.w + r * gh_n.w);
                o.w = (1.0f - z) * n + z * xv.w;
            }
            *(float4*)(aux3 + (size_t)gr * HDIM + c4 * 4) = o;
        }
    } else {
        // LSTM (compact [i,g,o]): c=sig(i)*tanh(g); h=sig(o)*tanh(c); relu
#pragma unroll
        for (int p = 0; p < 16; p++) {
            int idx = p * 256 + tid;
            int row = idx >> 5;
            int c4 = idx & 31;
            int gr = row0 + row;
            if (gr >= M) continue;
            const float* cr = C + (size_t)gr * 384 + c4 * 4;
            float4 ig = __ldcg((const float4*)(cr));
            float4 gg = __ldcg((const float4*)(cr + 128));
            float4 og = __ldcg((const float4*)(cr + 256));
            float4 o;
            o.x = fmaxf(sigf(og.x) * tanhf(sigf(ig.x) * tanhf(gg.x)), 0.0f);
            o.y = fmaxf(sigf(og.y) * tanhf(sigf(ig.y) * tanhf(gg.y)), 0.0f);
            o.z = fmaxf(sigf(og.z) * tanhf(sigf(ig.z) * tanhf(gg.z)), 0.0f);
            o.w = fmaxf(sigf(og.w) * tanhf(sigf(ig.w) * tanhf(gg.w)), 0.0f);
            *(float4*)(aux3 + (size_t)gr * HDIM + c4 * 4) = o;
        }
    }
}

// ---------------- host orchestration -----------------------------------------
extern "C" void kernel_launch(void* const* d_in, const int* in_sizes, int n_in,
                              void* d_out, int out_size) {
    const float* x = (const float*)d_in[0];
    const void* edges = d_in[1];
    const float* W = (const float*)d_in[2];
    const float* gru_w_ih = (const float*)d_in[3];
    const float* gru_w_hh = (const float*)d_in[4];
    const float* gru_b_ih = (const float*)d_in[5];
    const float* gru_b_hh = (const float*)d_in[6];
    const float* lstm_w_ih = (const float*)d_in[7];
    // d_in[8] lstm_w_hh dead (h0 = 0)
    const float* lstm_b_ih = (const float*)d_in[9];
    const float* lstm_b_hh = (const float*)d_in[10];
    float* out = (float*)d_out;

    const int M = in_sizes[0] / HDIM;
    const int E = in_sizes[1] / 2;

    float *pm, *pgh, *pagg, *pgi, *phc, *pgates, *pwt;
    cudaGetSymbolAddress((void**)&pm, g_m);
    cudaGetSymbolAddress((void**)&pgh, g_gh);
    cudaGetSymbolAddress((void**)&pagg, g_agg);
    cudaGetSymbolAddress((void**)&pgi, g_gi);
    cudaGetSymbolAddress((void**)&phc, g_hconv);
    cudaGetSymbolAddress((void**)&pgates, g_gates);
    cudaGetSymbolAddress((void**)&pwt, g_wt);

    cudaFuncSetAttribute(mma_gemm_kernel,
                         cudaFuncAttributeMaxDynamicSharedMemorySize, SMEM_BYTES);

    const int rowTiles = (M + 127) / 128;

    // 1) prep
    detect_kernel<<<1, 1>>>(edges);
    zero_deg_kernel<<<(M + 255) / 256, 256>>>(M);
    transposeW_kernel<<<(HDIM * HDIM + 255) / 256, 256>>>(W);

    // 2) m = x @ W
    mma_gemm_kernel<<<rowTiles, 256, SMEM_BYTES>>>(
        x, pwt, (const float*)0, (const float*)0, pm, M, HDIM, 2, 0,
        0, (const float*)0, (const float*)0, (float*)0);

    // 3) gh = x @ gru_w_hh^T + b_hh
    mma_gemm_kernel<<<rowTiles, 256, SMEM_BYTES>>>(
        x, gru_w_hh, gru_b_hh, (const float*)0, pgh, M, 3 * HDIM, 6, 0,
        0, (const float*)0, (const float*)0, (float*)0);

    // 4) CSR build + gather (mean fused)
    hist_kernel<<<4096, 256>>>(edges, E);
    scan_kernel<<<1, 1024>>>(M);
    fill_kernel<<<4096, 256>>>(edges, E);
    gather_kernel<<<(M * 32 + 255) / 256, 256>>>(pm, M);

    // 5) gi = agg @ gru_w_ih^T + b_ih  ... fused GRU -> hconv
    mma_gemm_kernel<<<rowTiles, 256, SMEM_BYTES>>>(
        pagg, gru_w_ih, gru_b_ih, (const float*)0, pgi, M, 3 * HDIM, 6, 0,
        1, pgh, x, phc);

    // 6) gates = hconv @ lstm_w_ih^T + b (f skipped) ... fused LSTM -> out
    mma_gemm_kernel<<<rowTiles, 256, SMEM_BYTES>>>(
        phc, lstm_w_ih, lstm_b_ih, lstm_b_hh, pgates, M, 3 * HDIM, 6, 1,
        2, (const float*)0, (const float*)0, out);
}

// round 13
// speedup vs baseline: 2.3401x; 1.0521x over previous
#include <cuda_runtime.h>
#include <cuda_bf16.h>
#include <cuda_fp16.h>
#include <cstdint>
#include <math.h>

// Problem constants
#define NN_MAX 100096
#define HDIM 128
#define EMAX 3400000

// ---------------- scratch (device globals; no allocation allowed) ------------
__device__ __half g_mh[NN_MAX * HDIM];          // x @ W   (fp16 messages)
__device__ float g_gh[NN_MAX * 3 * HDIM];       // x @ gru_w_hh^T + b_hh
__device__ float g_agg[NN_MAX * HDIM];          // mean-aggregated messages
__device__ float g_gi[NN_MAX * 3 * HDIM];       // agg @ gru_w_ih^T + b_ih
__device__ float g_hconv[NN_MAX * HDIM];        // GRU output
__device__ float g_gates[NN_MAX * 3 * HDIM];    // lstm gates, compact [i,g,o]
__device__ float g_wt[HDIM * HDIM];             // W^T
__device__ int   g_degi[NN_MAX];
__device__ int   g_cursor[NN_MAX];
__device__ int   g_off[NN_MAX + 1];
__device__ int   g_csr[EMAX];
__device__ int   g_idx64;

// ---------------- index-width detection --------------------------------------
__global__ void detect_kernel(const void* edges) {
    const int* p = (const int*)edges;
    int z = 0;
#pragma unroll
    for (int i = 0; i < 8; i++) z += (p[2 * i + 1] == 0) ? 1 : 0;
    g_idx64 = (z == 8) ? 1 : 0;
}

__global__ void zero_deg_kernel(int M) {
    int i = blockIdx.x * blockDim.x + threadIdx.x;
    if (i < M) g_degi[i] = 0;
}

__global__ void transposeW_kernel(const float* __restrict__ W) {
    int i = blockIdx.x * blockDim.x + threadIdx.x;
    if (i < HDIM * HDIM) {
        int r = i >> 7;
        int c = i & 127;
        g_wt[c * HDIM + r] = W[i];
    }
}

// ---------------- CSR build -----------------------------------------------
__global__ void hist_kernel(const void* __restrict__ edges, int E) {
    const bool is64 = (g_idx64 != 0);
    const long long* p64 = (const long long*)edges;
    const int* p32 = (const int*)edges;
    int stride = gridDim.x * blockDim.x;
    for (int e = blockIdx.x * blockDim.x + threadIdx.x; e < E; e += stride) {
        int dst = is64 ? (int)p64[E + e] : p32[E + e];
        atomicAdd(&g_degi[dst], 1);
    }
}

__global__ void scan_kernel(int M) {
    __shared__ int warpsums[32];
    const int tid = threadIdx.x;
    const int lane = tid & 31;
    const int wid = tid >> 5;
    int running = 0;
    for (int base = 0; base < M; base += 1024) {
        int i = base + tid;
        int v = (i < M) ? g_degi[i] : 0;
        int s = v;
#pragma unroll
        for (int o = 1; o < 32; o <<= 1) {
            int t = __shfl_up_sync(0xffffffffu, s, o);
            if (lane >= o) s += t;
        }
        if (lane == 31) warpsums[wid] = s;
        __syncthreads();
        if (wid == 0) {
            int ws = warpsums[lane];
#pragma unroll
            for (int o = 1; o < 32; o <<= 1) {
                int t = __shfl_up_sync(0xffffffffu, ws, o);
                if (lane >= o) ws += t;
            }
            warpsums[lane] = ws;
        }
        __syncthreads();
        int warpBase = (wid == 0) ? 0 : warpsums[wid - 1];
        int excl = running + warpBase + s - v;
        if (i < M) {
            g_off[i] = excl;
            g_cursor[i] = excl;
        }
        int chunkTotal = warpsums[31];
        __syncthreads();
        running += chunkTotal;
    }
    if (tid == 0) g_off[M] = running;
}

__global__ void fill_kernel(const void* __restrict__ edges, int E) {
    const bool is64 = (g_idx64 != 0);
    const long long* p64 = (const long long*)edges;
    const int* p32 = (const int*)edges;
    int stride = gridDim.x * blockDim.x;
    for (int e = blockIdx.x * blockDim.x + threadIdx.x; e < E; e += stride) {
        int src, dst;
        if (is64) {
            src = (int)p64[e];
            dst = (int)p64[E + e];
        } else {
            src = p32[e];
            dst = p32[E + e];
        }
        int pos = atomicAdd(&g_cursor[dst], 1);
        g_csr[pos] = src;
    }
}

// ---------------- gather: one warp per dst, fp16 messages, mean fused ---------
__global__ void gather_kernel(const __half* __restrict__ mh, int M) {
    int w = (blockIdx.x * blockDim.x + threadIdx.x) >> 5;
    if (w >= M) return;
    int lane = threadIdx.x & 31;
    int start = g_off[w];
    int end = g_off[w + 1];
    float ax = 0.f, ay = 0.f, az = 0.f, aw = 0.f;
    int e = start;
    for (; e + 3 < end; e += 4) {
#pragma unroll
        for (int q = 0; q < 4; q++) {
            int s0 = g_csr[e + q];
            uint2 u = *(const uint2*)(mh + (size_t)s0 * HDIM + lane * 4);
            float2 f0 = __half22float2(*reinterpret_cast<__half2*>(&u.x));
            float2 f1 = __half22float2(*reinterpret_cast<__half2*>(&u.y));
            ax += f0.x; ay += f0.y; az += f1.x; aw += f1.y;
        }
    }
    for (; e < end; e++) {
        int s0 = g_csr[e];
        uint2 u = *(const uint2*)(mh + (size_t)s0 * HDIM + lane * 4);
        float2 f0 = __half22float2(*reinterpret_cast<__half2*>(&u.x));
        float2 f1 = __half22float2(*reinterpret_cast<__half2*>(&u.y));
        ax += f0.x; ay += f0.y; az += f1.x; aw += f1.y;
    }
    float inv = 1.0f / fmaxf((float)(end - start), 1.0f);
    float4 o = make_float4(ax * inv, ay * inv, az * inv, aw * inv);
    *(float4*)(g_agg + (size_t)w * HDIM + lane * 4) = o;
}

// =====================================================================
// bf16x3 tensor-core GEMM (mma.sync path; tcgen05 rejected by harness's
// compute_103 virtual arch). In-block col-tile loop, A loaded+split once.
// Two output phases:
//   phase 1 (t < nT1): B1 tiles -> C1h (fp16 store, no bias)   [m = x@W]
//   phase 2:           B2 tiles -> C2 (fp32 + bias(+bias2))
// gateSkip (phase 2): tile tt reads B2 rows {0,64,256,320,384,448}[tt].
// =====================================================================
#define SROW 136
#define OFF_A_HI 0
#define OFF_A_LO (128 * SROW * 2)
#define OFF_B_HI (2 * 128 * SROW * 2)
#define OFF_B_LO (2 * 128 * SROW * 2 + 64 * SROW * 2)
#define SMEM_BYTES (2 * 128 * SROW * 2 + 2 * 64 * SROW * 2)

__device__ __forceinline__ void ldsm4(uint32_t& r0, uint32_t& r1, uint32_t& r2,
                                      uint32_t& r3, uint32_t addr) {
    asm volatile("ldmatrix.sync.aligned.m8n8.x4.shared.b16 {%0,%1,%2,%3}, [%4];"
                 : "=r"(r0), "=r"(r1), "=r"(r2), "=r"(r3) : "r"(addr));
}

__device__ __forceinline__ void mma_bf16(float* c, const uint32_t* a,
                                         uint32_t b0, uint32_t b1) {
    asm volatile(
        "mma.sync.aligned.m16n8k16.row.col.f32.bf16.bf16.f32 "
        "{%0,%1,%2,%3}, {%4,%5,%6,%7}, {%8,%9}, {%0,%1,%2,%3};"
        : "+f"(c[0]), "+f"(c[1]), "+f"(c[2]), "+f"(c[3])
        : "r"(a[0]), "r"(a[1]), "r"(a[2]), "r"(a[3]), "r"(b0), "r"(b1));
}

__device__ __forceinline__ void split_pack(float x, float y,
                                           uint32_t& hi, uint32_t& lo) {
    __nv_bfloat16 hx = __float2bfloat16_rn(x);
    __nv_bfloat16 hy = __float2bfloat16_rn(y);
    __nv_bfloat16 lx = __float2bfloat16_rn(x - __bfloat162float(hx));
    __nv_bfloat16 ly = __float2bfloat16_rn(y - __bfloat162float(hy));
    hi = ((uint32_t)__bfloat16_as_ushort(hy) << 16) | (uint32_t)__bfloat16_as_ushort(hx);
    lo = ((uint32_t)__bfloat16_as_ushort(ly) << 16) | (uint32_t)__bfloat16_as_ushort(lx);
}

__global__ __launch_bounds__(256, 2)
void mma_gemm_kernel(const float* __restrict__ A,
                     const float* __restrict__ B1, __half* __restrict__ C1h,
                     int N1, int nT1,
                     const float* __restrict__ B2, const float* __restrict__ bias,
                     const float* __restrict__ bias2, float* __restrict__ C2,
                     int N2, int nT2, int gateSkip, int M) {
    extern __shared__ char smem[];
    const uint32_t sbase = (uint32_t)__cvta_generic_to_shared(smem);
    const int tid = threadIdx.x;
    const int lane = tid & 31;
    const int wid = tid >> 5;
    const int row0 = blockIdx.x * 128;

    // ---- load + split A tile ONCE -------------------------------------------
    {
        uint32_t* shi = (uint32_t*)(smem + OFF_A_HI);
        uint32_t* slo = (uint32_t*)(smem + OFF_A_LO);
#pragma unroll
        for (int p = 0; p < 16; p++) {
            int idx = p * 256 + tid;
            int row = idx >> 5;
            int k4 = idx & 31;
            int gr = row0 + row;
            float4 v = make_float4(0.f, 0.f, 0.f, 0.f);
            if (gr < M) v = *(const float4*)(A + (size_t)gr * HDIM + k4 * 4);
            uint32_t h0, l0, h1, l1;
            split_pack(v.x, v.y, h0, l0);
            split_pack(v.z, v.w, h1, l1);
            int o = row * (SROW / 2) + k4 * 2;
            shi[o] = h0; shi[o + 1] = h1;
            slo[o] = l0; slo[o + 1] = l1;
        }
    }

    const int wm = wid >> 1;
    const int wn = wid & 1;
    const int a_row_in = ((lane >> 3) & 1) * 8 + (lane & 7);
    const int a_kh = (lane >> 4) * 8;
    const int b_row_in = ((lane >> 4) & 1) * 8 + (lane & 7);
    const int b_kh = ((lane >> 3) & 1) * 8;

    const int nTot = nT1 + nT2;
    for (int t = 0; t < nTot; t++) {
        const bool ph1 = (t < nT1);
        const int tt = ph1 ? t : t - nT1;
        const float* Bp = ph1 ? B1 : B2;
        const int brow0 = ph1 ? tt * 64
                              : (gateSkip ? ((tt < 2) ? tt * 64 : (tt + 2) * 64)
                                          : tt * 64);
        const int ccol0 = tt * 64;

        if (t > 0) __syncthreads();   // previous compute done before B overwrite

        // ---- load + split B tile: 64 rows x 128 k ---------------------------
        {
            uint32_t* shi = (uint32_t*)(smem + OFF_B_HI);
            uint32_t* slo = (uint32_t*)(smem + OFF_B_LO);
#pragma unroll
            for (int p = 0; p < 8; p++) {
                int idx = p * 256 + tid;
                int row = idx >> 5;
                int k4 = idx & 31;
                float4 v = *(const float4*)(Bp + (size_t)(brow0 + row) * HDIM + k4 * 4);
                uint32_t h0, l0, h1, l1;
                split_pack(v.x, v.y, h0, l0);
                split_pack(v.z, v.w, h1, l1);
                int o = row * (SROW / 2) + k4 * 2;
                shi[o] = h0; shi[o + 1] = h1;
                slo[o] = l0; slo[o + 1] = l1;
            }
        }
        __syncthreads();

        float acc[2][4][4];
#pragma unroll
        for (int i = 0; i < 2; i++)
#pragma unroll
            for (int j = 0; j < 4; j++)
#pragma unroll
                for (int q = 0; q < 4; q++) acc[i][j][q] = 0.0f;

#pragma unroll 2
        for (int kc = 0; kc < 8; kc++) {
            const int k0 = kc * 16;
            uint32_t ah[2][4], al[2][4];
#pragma unroll
            for (int i = 0; i < 2; i++) {
                int row = wm * 32 + i * 16 + a_row_in;
                uint32_t off = (uint32_t)(row * (SROW * 2) + (k0 + a_kh) * 2);
                ldsm4(ah[i][0], ah[i][1], ah[i][2], ah[i][3], sbase + OFF_A_HI + off);
                ldsm4(al[i][0], al[i][1], al[i][2], al[i][3], sbase + OFF_A_LO + off);
            }
            uint32_t bh[2][4], bl[2][4];
#pragma unroll
            for (int p = 0; p < 2; p++) {
                int row = wn * 32 + p * 16 + b_row_in;
                uint32_t off = (uint32_t)(row * (SROW * 2) + (k0 + b_kh) * 2);
                ldsm4(bh[p][0], bh[p][1], bh[p][2], bh[p][3], sbase + OFF_B_HI + off);
                ldsm4(bl[p][0], bl[p][1], bl[p][2], bl[p][3], sbase + OFF_B_LO + off);
            }
#pragma unroll
            for (int i = 0; i < 2; i++) {
#pragma unroll
                for (int j = 0; j < 4; j++) {
                    const int p = j >> 1;
                    const int s = (j & 1) * 2;
                    mma_bf16(acc[i][j], ah[i], bh[p][s], bh[p][s + 1]);
                    mma_bf16(acc[i][j], ah[i], bl[p][s], bl[p][s + 1]);
                    mma_bf16(acc[i][j], al[i], bh[p][s], bh[p][s + 1]);
                }
            }
        }

        // ---- store tile -----------------------------------------------------
        if (ph1) {
#pragma unroll
            for (int j = 0; j < 4; j++) {
                int cb = ccol0 + wn * 32 + j * 8 + (lane & 3) * 2;
#pragma unroll
                for (int i = 0; i < 2; i++) {
                    int ra = row0 + wm * 32 + i * 16 + (lane >> 2);
                    if (ra < M) {
                        __half2 hv = __floats2half2_rn(acc[i][j][0], acc[i][j][1]);
                        *(__half2*)(C1h + (size_t)ra * N1 + cb) = hv;
                    }
                    int rb = ra + 8;
                    if (rb < M) {
                        __half2 hv = __floats2half2_rn(acc[i][j][2], acc[i][j][3]);
                        *(__half2*)(C1h + (size_t)rb * N1 + cb) = hv;
                    }
                }
            }
        } else {
#pragma unroll
            for (int j = 0; j < 4; j++) {
                int cloc = wn * 32 + j * 8 + (lane & 3) * 2;
                int cb = ccol0 + cloc;
                int bidx = brow0 + cloc;
                float b0 = 0.f, b1 = 0.f;
                if (bias)  { b0 += __ldg(bias + bidx);  b1 += __ldg(bias + bidx + 1); }
                if (bias2) { b0 += __ldg(bias2 + bidx); b1 += __ldg(bias2 + bidx + 1); }
#pragma unroll
                for (int i = 0; i < 2; i++) {
                    int ra = row0 + wm * 32 + i * 16 + (lane >> 2);
                    if (ra < M) {
                        float2 o = make_float2(acc[i][j][0] + b0, acc[i][j][1] + b1);
                        *(float2*)(C2 + (size_t)ra * N2 + cb) = o;
                    }
                    int rb = ra + 8;
                    if (rb < M) {
                        float2 o = make_float2(acc[i][j][2] + b0, acc[i][j][3] + b1);
                        *(float2*)(C2 + (size_t)rb * N2 + cb) = o;
                    }
                }
            }
        }
    }
}

// ---------------- GRU elementwise (standalone, high occupancy) ----------------
__global__ void gru_elem_kernel(const float* __restrict__ x, int M) {
    int i = blockIdx.x * blockDim.x + threadIdx.x;
    if (i >= M * HDIM) return;
    int row = i >> 7;
    int j = i & 127;
    const float* gir = g_gi + (size_t)row * (3 * HDIM);
    const float* ghr = g_gh + (size_t)row * (3 * HDIM);
    float r = 1.0f / (1.0f + __expf(-(gir[j] + ghr[j])));
    float z = 1.0f / (1.0f + __expf(-(gir[j + 128] + ghr[j + 128])));
    float ng = tanhf(gir[j + 256] + r * ghr[j + 256]);
    g_hconv[i] = (1.0f - z) * ng + z * x[i];
}

// ---------------- LSTM elementwise (compact [i,g,o]) + ReLU -------------------
__global__ void lstm_elem_kernel(float* __restrict__ out, int M) {
    int i = blockIdx.x * blockDim.x + threadIdx.x;
    if (i >= M * HDIM) return;
    int row = i >> 7;
    int j = i & 127;
    const float* g = g_gates + (size_t)row * (3 * HDIM);
    float ig = g[j];
    float gg = g[j + 128];
    float og = g[j + 256];
    float c = (1.0f / (1.0f + __expf(-ig))) * tanhf(gg);
    float h = (1.0f / (1.0f + __expf(-og))) * tanhf(c);
    out[i] = fmaxf(h, 0.0f);
}

// ---------------- host orchestration -----------------------------------------
extern "C" void kernel_launch(void* const* d_in, const int* in_sizes, int n_in,
                              void* d_out, int out_size) {
    const float* x = (const float*)d_in[0];
    const void* edges = d_in[1];
    const float* W = (const float*)d_in[2];
    const float* gru_w_ih = (const float*)d_in[3];
    const float* gru_w_hh = (const float*)d_in[4];
    const float* gru_b_ih = (const float*)d_in[5];
    const float* gru_b_hh = (const float*)d_in[6];
    const float* lstm_w_ih = (const float*)d_in[7];
    // d_in[8] lstm_w_hh dead (h0 = 0)
    const float* lstm_b_ih = (const float*)d_in[9];
    const float* lstm_b_hh = (const float*)d_in[10];
    float* out = (float*)d_out;

    const int M = in_sizes[0] / HDIM;
    const int E = in_sizes[1] / 2;

    float *pgh, *pagg, *pgi, *phc, *pgates, *pwt;
    __half* pmh;
    cudaGetSymbolAddress((void**)&pmh, g_mh);
    cudaGetSymbolAddress((void**)&pgh, g_gh);
    cudaGetSymbolAddress((void**)&pagg, g_agg);
    cudaGetSymbolAddress((void**)&pgi, g_gi);
    cudaGetSymbolAddress((void**)&phc, g_hconv);
    cudaGetSymbolAddress((void**)&pgates, g_gates);
    cudaGetSymbolAddress((void**)&pwt, g_wt);

    cudaFuncSetAttribute(mma_gemm_kernel,
                         cudaFuncAttributeMaxDynamicSharedMemorySize, SMEM_BYTES);

    const int rowTiles = (M + 127) / 128;

    // 1) prep
    detect_kernel<<<1, 1>>>(edges);
    zero_deg_kernel<<<(M + 255) / 256, 256>>>(M);
    transposeW_kernel<<<(HDIM * HDIM + 255) / 256, 256>>>(W);

    // 2) merged: m(fp16) = x @ W  AND  gh = x @ gru_w_hh^T + b_hh  (A once)
    mma_gemm_kernel<<<rowTiles, 256, SMEM_BYTES>>>(
        x,
        pwt, pmh, HDIM, 2,
        gru_w_hh, gru_b_hh, (const float*)0, pgh, 3 * HDIM, 6,
        0, M);

    // 3) CSR build + gather (fp16 messages, mean fused)
    hist_kernel<<<4096, 256>>>(edges, E);
    scan_kernel<<<1, 1024>>>(M);
    fill_kernel<<<4096, 256>>>(edges, E);
    gather_kernel<<<(M * 32 + 255) / 256, 256>>>(pmh, M);

    // 4) gi = agg @ gru_w_ih^T + b_ih
    mma_gemm_kernel<<<rowTiles, 256, SMEM_BYTES>>>(
        pagg,
        (const float*)0, (__half*)0, 0, 0,
        gru_w_ih, gru_b_ih, (const float*)0, pgi, 3 * HDIM, 6,
        0, M);

    // 5) GRU combine -> hconv
    gru_elem_kernel<<<(M * HDIM + 255) / 256, 256>>>(x, M);

    // 6) gates = hconv @ lstm_w_ih^T + b (f-gate skipped, compact [i,g,o])
    mma_gemm_kernel<<<rowTiles, 256, SMEM_BYTES>>>(
        phc,
        (const float*)0, (__half*)0, 0, 0,
        lstm_w_ih, lstm_b_ih, lstm_b_hh, pgates, 3 * HDIM, 6,
        1, M);

    // 7) LSTM + ReLU -> out
    lstm_elem_kernel<<<(M * HDIM + 255) / 256, 256>>>(out, M);
}

// round 14
// speedup vs baseline: 2.6399x; 1.1281x over previous
#include <cuda_runtime.h>
#include <cuda_fp16.h>
#include <cstdint>
#include <math.h>

// Problem constants
#define NN_MAX 100096
#define HDIM 128
#define EMAX 3400000

// ---------------- scratch (device globals; no allocation allowed) ------------
__device__ __half g_mh[NN_MAX * HDIM];          // x @ W   (fp16 messages)
__device__ float g_gh[NN_MAX * 3 * HDIM];       // x @ gru_w_hh^T + b_hh
__device__ float g_agg[NN_MAX * HDIM];          // mean-aggregated messages
__device__ float g_gi[NN_MAX * 3 * HDIM];       // agg @ gru_w_ih^T + b_ih
__device__ float g_hconv[NN_MAX * HDIM];        // GRU output
__device__ float g_gates[NN_MAX * 3 * HDIM];    // lstm gates, compact [i,g,o]
__device__ float g_wt[HDIM * HDIM];             // W^T
__device__ int   g_degi[NN_MAX];
__device__ int   g_cursor[NN_MAX];
__device__ int   g_off[NN_MAX + 1];
__device__ int   g_csr[EMAX];
__device__ int   g_idx64;

// ---------------- index-width detection --------------------------------------
__global__ void detect_kernel(const void* edges) {
    const int* p = (const int*)edges;
    int z = 0;
#pragma unroll
    for (int i = 0; i < 8; i++) z += (p[2 * i + 1] == 0) ? 1 : 0;
    g_idx64 = (z == 8) ? 1 : 0;
}

__global__ void zero_deg_kernel(int M) {
    int i = blockIdx.x * blockDim.x + threadIdx.x;
    if (i < M) g_degi[i] = 0;
}

__global__ void transposeW_kernel(const float* __restrict__ W) {
    int i = blockIdx.x * blockDim.x + threadIdx.x;
    if (i < HDIM * HDIM) {
        int r = i >> 7;
        int c = i & 127;
        g_wt[c * HDIM + r] = W[i];
    }
}

// ---------------- CSR build -----------------------------------------------
__global__ void hist_kernel(const void* __restrict__ edges, int E) {
    const bool is64 = (g_idx64 != 0);
    const long long* p64 = (const long long*)edges;
    const int* p32 = (const int*)edges;
    int stride = gridDim.x * blockDim.x;
    for (int e = blockIdx.x * blockDim.x + threadIdx.x; e < E; e += stride) {
        int dst = is64 ? (int)p64[E + e] : p32[E + e];
        atomicAdd(&g_degi[dst], 1);
    }
}

__global__ void scan_kernel(int M) {
    __shared__ int warpsums[32];
    const int tid = threadIdx.x;
    const int lane = tid & 31;
    const int wid = tid >> 5;
    int running = 0;
    for (int base = 0; base < M; base += 1024) {
        int i = base + tid;
        int v = (i < M) ? g_degi[i] : 0;
        int s = v;
#pragma unroll
        for (int o = 1; o < 32; o <<= 1) {
            int t = __shfl_up_sync(0xffffffffu, s, o);
            if (lane >= o) s += t;
        }
        if (lane == 31) warpsums[wid] = s;
        __syncthreads();
        if (wid == 0) {
            int ws = warpsums[lane];
#pragma unroll
            for (int o = 1; o < 32; o <<= 1) {
                int t = __shfl_up_sync(0xffffffffu, ws, o);
                if (lane >= o) ws += t;
            }
            warpsums[lane] = ws;
        }
        __syncthreads();
        int warpBase = (wid == 0) ? 0 : warpsums[wid - 1];
        int excl = running + warpBase + s - v;
        if (i < M) {
            g_off[i] = excl;
            g_cursor[i] = excl;
        }
        int chunkTotal = warpsums[31];
        __syncthreads();
        running += chunkTotal;
    }
    if (tid == 0) g_off[M] = running;
}

__global__ void fill_kernel(const void* __restrict__ edges, int E) {
    const bool is64 = (g_idx64 != 0);
    const long long* p64 = (const long long*)edges;
    const int* p32 = (const int*)edges;
    int stride = gridDim.x * blockDim.x;
    for (int e = blockIdx.x * blockDim.x + threadIdx.x; e < E; e += stride) {
        int src, dst;
        if (is64) {
            src = (int)p64[e];
            dst = (int)p64[E + e];
        } else {
            src = p32[e];
            dst = p32[E + e];
        }
        int pos = atomicAdd(&g_cursor[dst], 1);
        g_csr[pos] = src;
    }
}

// ---------------- gather: one warp per dst, fp16 messages, mean fused ---------
__global__ void gather_kernel(const __half* __restrict__ mh, int M) {
    int w = (blockIdx.x * blockDim.x + threadIdx.x) >> 5;
    if (w >= M) return;
    int lane = threadIdx.x & 31;
    int start = g_off[w];
    int end = g_off[w + 1];
    float ax = 0.f, ay = 0.f, az = 0.f, aw = 0.f;
    int e = start;
    for (; e + 3 < end; e += 4) {
#pragma unroll
        for (int q = 0; q < 4; q++) {
            int s0 = g_csr[e + q];
            uint2 u = *(const uint2*)(mh + (size_t)s0 * HDIM + lane * 4);
            float2 f0 = __half22float2(*reinterpret_cast<__half2*>(&u.x));
            float2 f1 = __half22float2(*reinterpret_cast<__half2*>(&u.y));
            ax += f0.x; ay += f0.y; az += f1.x; aw += f1.y;
        }
    }
    for (; e < end; e++) {
        int s0 = g_csr[e];
        uint2 u = *(const uint2*)(mh + (size_t)s0 * HDIM + lane * 4);
        float2 f0 = __half22float2(*reinterpret_cast<__half2*>(&u.x));
        float2 f1 = __half22float2(*reinterpret_cast<__half2*>(&u.y));
        ax += f0.x; ay += f0.y; az += f1.x; aw += f1.y;
    }
    float inv = 1.0f / fmaxf((float)(end - start), 1.0f);
    float4 o = make_float4(ax * inv, ay * inv, az * inv, aw * inv);
    *(float4*)(g_agg + (size_t)w * HDIM + lane * 4) = o;
}

// =====================================================================
// fp16 two-term tensor-core GEMM (mma.sync path).
//   A = Ahi + Alo (fp16 pair, exact to 2^-24); B = fp16(B) single.
//   C = Ahi*B + Alo*B  — only dropped term is A*Blo (~2.4e-4 rel).
// In-block col-tile loop, A loaded+split once. Two output phases:
//   phase 1 (t < nT1): B1 tiles -> C1h (fp16 store, no bias)   [m = x@W]
//   phase 2:           B2 tiles -> C2 (fp32 + bias(+bias2))
// gateSkip (phase 2): tile tt reads B2 rows {0,64,256,320,384,448}[tt].
// =====================================================================
#define SROW 136
#define OFF_A_HI 0
#define OFF_A_LO (128 * SROW * 2)
#define OFF_B    (2 * 128 * SROW * 2)
#define SMEM_BYTES (2 * 128 * SROW * 2 + 64 * SROW * 2)   // 87040

__device__ __forceinline__ void ldsm4(uint32_t& r0, uint32_t& r1, uint32_t& r2,
                                      uint32_t& r3, uint32_t addr) {
    asm volatile("ldmatrix.sync.aligned.m8n8.x4.shared.b16 {%0,%1,%2,%3}, [%4];"
                 : "=r"(r0), "=r"(r1), "=r"(r2), "=r"(r3) : "r"(addr));
}

__device__ __forceinline__ void mma_f16(float* c, const uint32_t* a,
                                        uint32_t b0, uint32_t b1) {
    asm volatile(
        "mma.sync.aligned.m16n8k16.row.col.f32.f16.f16.f32 "
        "{%0,%1,%2,%3}, {%4,%5,%6,%7}, {%8,%9}, {%0,%1,%2,%3};"
        : "+f"(c[0]), "+f"(c[1]), "+f"(c[2]), "+f"(c[3])
        : "r"(a[0]), "r"(a[1]), "r"(a[2]), "r"(a[3]), "r"(b0), "r"(b1));
}

// fp16 split: hi = h(x), lo = h(x - hi); packed pairs
__device__ __forceinline__ void split_pack_h(float x, float y,
                                             uint32_t& hi, uint32_t& lo) {
    __half hx = __float2half_rn(x);
    __half hy = __float2half_rn(y);
    __half lx = __float2half_rn(x - __half2float(hx));
    __half ly = __float2half_rn(y - __half2float(hy));
    hi = ((uint32_t)__half_as_ushort(hy) << 16) | (uint32_t)__half_as_ushort(hx);
    lo = ((uint32_t)__half_as_ushort(ly) << 16) | (uint32_t)__half_as_ushort(lx);
}

__device__ __forceinline__ uint32_t pack_h(float x, float y) {
    __half hx = __float2half_rn(x);
    __half hy = __float2half_rn(y);
    return ((uint32_t)__half_as_ushort(hy) << 16) | (uint32_t)__half_as_ushort(hx);
}

__global__ __launch_bounds__(256, 2)
void mma_gemm_kernel(const float* __restrict__ A,
                     const float* __restrict__ B1, __half* __restrict__ C1h,
                     int N1, int nT1,
                     const float* __restrict__ B2, const float* __restrict__ bias,
                     const float* __restrict__ bias2, float* __restrict__ C2,
                     int N2, int nT2, int gateSkip, int M) {
    extern __shared__ char smem[];
    const uint32_t sbase = (uint32_t)__cvta_generic_to_shared(smem);
    const int tid = threadIdx.x;
    const int lane = tid & 31;
    const int wid = tid >> 5;
    const int row0 = blockIdx.x * 128;

    // ---- load + split A tile ONCE -------------------------------------------
    {
        uint32_t* shi = (uint32_t*)(smem + OFF_A_HI);
        uint32_t* slo = (uint32_t*)(smem + OFF_A_LO);
#pragma unroll
        for (int p = 0; p < 16; p++) {
            int idx = p * 256 + tid;
            int row = idx >> 5;
            int k4 = idx & 31;
            int gr = row0 + row;
            float4 v = make_float4(0.f, 0.f, 0.f, 0.f);
            if (gr < M) v = *(const float4*)(A + (size_t)gr * HDIM + k4 * 4);
            uint32_t h0, l0, h1, l1;
            split_pack_h(v.x, v.y, h0, l0);
            split_pack_h(v.z, v.w, h1, l1);
            int o = row * (SROW / 2) + k4 * 2;
            shi[o] = h0; shi[o + 1] = h1;
            slo[o] = l0; slo[o + 1] = l1;
        }
    }

    const int wm = wid >> 1;
    const int wn = wid & 1;
    const int a_row_in = ((lane >> 3) & 1) * 8 + (lane & 7);
    const int a_kh = (lane >> 4) * 8;
    const int b_row_in = ((lane >> 4) & 1) * 8 + (lane & 7);
    const int b_kh = ((lane >> 3) & 1) * 8;

    const int nTot = nT1 + nT2;
    for (int t = 0; t < nTot; t++) {
        const bool ph1 = (t < nT1);
        const int tt = ph1 ? t : t - nT1;
        const float* Bp = ph1 ? B1 : B2;
        const int brow0 = ph1 ? tt * 64
                              : (gateSkip ? ((tt < 2) ? tt * 64 : (tt + 2) * 64)
                                          : tt * 64);
        const int ccol0 = tt * 64;

        if (t > 0) __syncthreads();   // previous compute done before B overwrite

        // ---- load B tile (single fp16 copy): 64 rows x 128 k ----------------
        {
            uint32_t* sb = (uint32_t*)(smem + OFF_B);
#pragma unroll
            for (int p = 0; p < 8; p++) {
                int idx = p * 256 + tid;
                int row = idx >> 5;
                int k4 = idx & 31;
                float4 v = *(const float4*)(Bp + (size_t)(brow0 + row) * HDIM + k4 * 4);
                int o = row * (SROW / 2) + k4 * 2;
                sb[o] = pack_h(v.x, v.y);
                sb[o + 1] = pack_h(v.z, v.w);
            }
        }
        __syncthreads();

        float acc[2][4][4];
#pragma unroll
        for (int i = 0; i < 2; i++)
#pragma unroll
            for (int j = 0; j < 4; j++)
#pragma unroll
                for (int q = 0; q < 4; q++) acc[i][j][q] = 0.0f;

#pragma unroll 2
        for (int kc = 0; kc < 8; kc++) {
            const int k0 = kc * 16;
            uint32_t ah[2][4], al[2][4];
#pragma unroll
            for (int i = 0; i < 2; i++) {
                int row = wm * 32 + i * 16 + a_row_in;
                uint32_t off = (uint32_t)(row * (SROW * 2) + (k0 + a_kh) * 2);
                ldsm4(ah[i][0], ah[i][1], ah[i][2], ah[i][3], sbase + OFF_A_HI + off);
                ldsm4(al[i][0], al[i][1], al[i][2], al[i][3], sbase + OFF_A_LO + off);
            }
            uint32_t bh[2][4];
#pragma unroll
            for (int p = 0; p < 2; p++) {
                int row = wn * 32 + p * 16 + b_row_in;
                uint32_t off = (uint32_t)(row * (SROW * 2) + (k0 + b_kh) * 2);
                ldsm4(bh[p][0], bh[p][1], bh[p][2], bh[p][3], sbase + OFF_B + off);
            }
#pragma unroll
            for (int i = 0; i < 2; i++) {
#pragma unroll
                for (int j = 0; j < 4; j++) {
                    const int p = j >> 1;
                    const int s = (j & 1) * 2;
                    mma_f16(acc[i][j], ah[i], bh[p][s], bh[p][s + 1]);
                    mma_f16(acc[i][j], al[i], bh[p][s], bh[p][s + 1]);
                }
            }
        }

        // ---- store tile -----------------------------------------------------
        if (ph1) {
#pragma unroll
            for (int j = 0; j < 4; j++) {
                int cb = ccol0 + wn * 32 + j * 8 + (lane & 3) * 2;
#pragma unroll
                for (int i = 0; i < 2; i++) {
                    int ra = row0 + wm * 32 + i * 16 + (lane >> 2);
                    if (ra < M) {
                        __half2 hv = __floats2half2_rn(acc[i][j][0], acc[i][j][1]);
                        *(__half2*)(C1h + (size_t)ra * N1 + cb) = hv;
                    }
                    int rb = ra + 8;
                    if (rb < M) {
                        __half2 hv = __floats2half2_rn(acc[i][j][2], acc[i][j][3]);
                        *(__half2*)(C1h + (size_t)rb * N1 + cb) = hv;
                    }
                }
            }
        } else {
#pragma unroll
            for (int j = 0; j < 4; j++) {
                int cloc = wn * 32 + j * 8 + (lane & 3) * 2;
                int cb = ccol0 + cloc;
                int bidx = brow0 + cloc;
                float b0 = 0.f, b1 = 0.f;
                if (bias)  { b0 += __ldg(bias + bidx);  b1 += __ldg(bias + bidx + 1); }
                if (bias2) { b0 += __ldg(bias2 + bidx); b1 += __ldg(bias2 + bidx + 1); }
#pragma unroll
                for (int i = 0; i < 2; i++) {
                    int ra = row0 + wm * 32 + i * 16 + (lane >> 2);
                    if (ra < M) {
                        float2 o = make_float2(acc[i][j][0] + b0, acc[i][j][1] + b1);
                        *(float2*)(C2 + (size_t)ra * N2 + cb) = o;
                    }
                    int rb = ra + 8;
                    if (rb < M) {
                        float2 o = make_float2(acc[i][j][2] + b0, acc[i][j][3] + b1);
                        *(float2*)(C2 + (size_t)rb * N2 + cb) = o;
                    }
                }
            }
        }
    }
}

// ---------------- GRU elementwise (standalone, high occupancy) ----------------
__global__ void gru_elem_kernel(const float* __restrict__ x, int M) {
    int i = blockIdx.x * blockDim.x + threadIdx.x;
    if (i >= M * HDIM) return;
    int row = i >> 7;
    int j = i & 127;
    const float* gir = g_gi + (size_t)row * (3 * HDIM);
    const float* ghr = g_gh + (size_t)row * (3 * HDIM);
    float r = 1.0f / (1.0f + __expf(-(gir[j] + ghr[j])));
    float z = 1.0f / (1.0f + __expf(-(gir[j + 128] + ghr[j + 128])));
    float ng = tanhf(gir[j + 256] + r * ghr[j + 256]);
    g_hconv[i] = (1.0f - z) * ng + z * x[i];
}

// ---------------- LSTM elementwise (compact [i,g,o]) + ReLU -------------------
__global__ void lstm_elem_kernel(float* __restrict__ out, int M) {
    int i = blockIdx.x * blockDim.x + threadIdx.x;
    if (i >= M * HDIM) return;
    int row = i >> 7;
    int j = i & 127;
    const float* g = g_gates + (size_t)row * (3 * HDIM);
    float ig = g[j];
    float gg = g[j + 128];
    float og = g[j + 256];
    float c = (1.0f / (1.0f + __expf(-ig))) * tanhf(gg);
    float h = (1.0f / (1.0f + __expf(-og))) * tanhf(c);
    out[i] = fmaxf(h, 0.0f);
}

// ---------------- host orchestration -----------------------------------------
extern "C" void kernel_launch(void* const* d_in, const int* in_sizes, int n_in,
                              void* d_out, int out_size) {
    const float* x = (const float*)d_in[0];
    const void* edges = d_in[1];
    const float* W = (const float*)d_in[2];
    const float* gru_w_ih = (const float*)d_in[3];
    const float* gru_w_hh = (const float*)d_in[4];
    const float* gru_b_ih = (const float*)d_in[5];
    const float* gru_b_hh = (const float*)d_in[6];
    const float* lstm_w_ih = (const float*)d_in[7];
    // d_in[8] lstm_w_hh dead (h0 = 0)
    const float* lstm_b_ih = (const float*)d_in[9];
    const float* lstm_b_hh = (const float*)d_in[10];
    float* out = (float*)d_out;

    const int M = in_sizes[0] / HDIM;
    const int E = in_sizes[1] / 2;

    float *pgh, *pagg, *pgi, *phc, *pgates, *pwt;
    __half* pmh;
    cudaGetSymbolAddress((void**)&pmh, g_mh);
    cudaGetSymbolAddress((void**)&pgh, g_gh);
    cudaGetSymbolAddress((void**)&pagg, g_agg);
    cudaGetSymbolAddress((void**)&pgi, g_gi);
    cudaGetSymbolAddress((void**)&phc, g_hconv);
    cudaGetSymbolAddress((void**)&pgates, g_gates);
    cudaGetSymbolAddress((void**)&pwt, g_wt);

    cudaFuncSetAttribute(mma_gemm_kernel,
                         cudaFuncAttributeMaxDynamicSharedMemorySize, SMEM_BYTES);

    const int rowTiles = (M + 127) / 128;

    // 1) prep
    detect_kernel<<<1, 1>>>(edges);
    zero_deg_kernel<<<(M + 255) / 256, 256>>>(M);
    transposeW_kernel<<<(HDIM * HDIM + 255) / 256, 256>>>(W);

    // 2) merged: m(fp16) = x @ W  AND  gh = x @ gru_w_hh^T + b_hh  (A once)
    mma_gemm_kernel<<<rowTiles, 256, SMEM_BYTES>>>(
        x,
        pwt, pmh, HDIM, 2,
        gru_w_hh, gru_b_hh, (const float*)0, pgh, 3 * HDIM, 6,
        0, M);

    // 3) CSR build + gather (fp16 messages, mean fused)
    hist_kernel<<<4096, 256>>>(edges, E);
    scan_kernel<<<1, 1024>>>(M);
    fill_kernel<<<4096, 256>>>(edges, E);
    gather_kernel<<<(M * 32 + 255) / 256, 256>>>(pmh, M);

    // 4) gi = agg @ gru_w_ih^T + b_ih
    mma_gemm_kernel<<<rowTiles, 256, SMEM_BYTES>>>(
        pagg,
        (const float*)0, (__half*)0, 0, 0,
        gru_w_ih, gru_b_ih, (const float*)0, pgi, 3 * HDIM, 6,
        0, M);

    // 5) GRU combine -> hconv
    gru_elem_kernel<<<(M * HDIM + 255) / 256, 256>>>(x, M);

    // 6) gates = hconv @ lstm_w_ih^T + b (f-gate skipped, compact [i,g,o])
    mma_gemm_kernel<<<rowTiles, 256, SMEM_BYTES>>>(
        phc,
        (const float*)0, (__half*)0, 0, 0,
        lstm_w_ih, lstm_b_ih, lstm_b_hh, pgates, 3 * HDIM, 6,
        1, M);

    // 7) LSTM + ReLU -> out
    lstm_elem_kernel<<<(M * HDIM + 255) / 256, 256>>>(out, M);
}